// round 1
// baseline (speedup 1.0000x reference)
#include <cuda_runtime.h>
#include <math.h>

// Problem shapes (fixed by the reference setup_inputs)
#define BSZ   32
#define LEN   8192
#define DD    64
#define HID   256
#define ROWS  (BSZ * LEN)          // 262144 rows of dim 64

// mu kernel tiling
#define TM    32                   // rows per block

// iteration kernel tiling
#define TL    64                   // L-rows per block (interior)
#define HALO  6                    // K iterations -> halo 6 each side
#define HTOT  (TL + 2*HALO)        // 76
#define HELEMS (HTOT * DD)         // 4864

// Scratch (device globals: no allocation allowed in kernel_launch)
__device__ float g_mu[(size_t)ROWS * DD];            // 64 MB
__device__ float g_epart[BSZ * (LEN / TL)];          // 32 x 128 partials

// ---------------------------------------------------------------------------
// Kernel 1: mu = softplus(relu([A;B]@W1+b1)@W2+b2) * (1 + 0.5*tanh(q@Wq+bq))
// Block: 256 threads, TM=32 rows. Stage 1: each thread owns one hidden column
// (j = tid) and accumulates all 32 rows in registers (x broadcast from smem,
// W1 row coalesced from L2). Stage 2/3: thread owns (out col j2 = tid&63,
// row group tid>>6 of 8 rows).
// ---------------------------------------------------------------------------
__global__ void __launch_bounds__(256) mu_kernel(
        const float* __restrict__ A,  const float* __restrict__ Bm,
        const float* __restrict__ q,
        const float* __restrict__ W1, const float* __restrict__ b1,
        const float* __restrict__ W2, const float* __restrict__ b2,
        const float* __restrict__ Wq, const float* __restrict__ bq)
{
    extern __shared__ float sm[];
    float* sx  = sm;                    // [TM][128]  concat(A,B)
    float* sq  = sx + TM * 128;         // [TM][64]
    float* sh1 = sq + TM * 64;          // [TM][256]  relu hidden

    const int tid = threadIdx.x;
    const size_t row0 = (size_t)blockIdx.x * TM;

    // Load inputs for this row tile
    for (int i = tid; i < TM * DD; i += 256) {
        int r = i >> 6, c = i & 63;
        size_t g = (row0 + r) * DD + c;
        sx[r * 128 + c]      = A[g];
        sx[r * 128 + 64 + c] = Bm[g];
        sq[r * 64 + c]       = q[g];
    }
    __syncthreads();

    // Stage 1: hidden layer. j = tid in [0,256)
    {
        float acc[TM];
#pragma unroll
        for (int r = 0; r < TM; r++) acc[r] = 0.f;
        const int j = tid;
#pragma unroll 4
        for (int k = 0; k < 128; k++) {
            float w = W1[k * HID + j];
#pragma unroll
            for (int r = 0; r < TM; r++) acc[r] += sx[r * 128 + k] * w;
        }
        float bb = b1[j];
#pragma unroll
        for (int r = 0; r < TM; r++) sh1[r * HID + j] = fmaxf(acc[r] + bb, 0.f);
    }
    __syncthreads();

    // Stage 2: mu_pre = h1 @ W2 + b2 ; Stage 3: gate = tanh(q @ Wq + bq)
    const int j2 = tid & 63;      // output column
    const int rg = tid >> 6;      // row group 0..3, rows rg*8 .. rg*8+7

    float acc2[8];
#pragma unroll
    for (int r = 0; r < 8; r++) acc2[r] = 0.f;
#pragma unroll 4
    for (int k = 0; k < HID; k++) {
        float w = W2[k * DD + j2];
#pragma unroll
        for (int r = 0; r < 8; r++) acc2[r] += sh1[(rg * 8 + r) * HID + k] * w;
    }

    float acc3[8];
#pragma unroll
    for (int r = 0; r < 8; r++) acc3[r] = 0.f;
#pragma unroll 4
    for (int k = 0; k < DD; k++) {
        float w = Wq[k * DD + j2];
#pragma unroll
        for (int r = 0; r < 8; r++) acc3[r] += sq[(rg * 8 + r) * DD + k] * w;
    }

    const float b2v = b2[j2], bqv = bq[j2];
#pragma unroll
    for (int r = 0; r < 8; r++) {
        float m = acc2[r] + b2v;
        m = (m > 20.f) ? m : log1pf(expf(m));      // softplus
        float g = tanhf(acc3[r] + bqv);
        g_mu[(row0 + rg * 8 + r) * DD + j2] = m * (1.f + 0.5f * g);
    }
}

// ---------------------------------------------------------------------------
// Kernel 2: K=6 fused iterations on D = A-B (with pointwise (1-0.3*mu) scale)
// and S = A+B (pure stencil), tile of TL L-rows with halo 6, circular in L.
// Writes hA, hB; per-block energy partial (deterministic).
// smooth(x)[l] = 0.9*x[l] + 0.05*(x[l-1] + x[l+1])
// ---------------------------------------------------------------------------
__global__ void __launch_bounds__(256) iter_kernel(
        const float* __restrict__ A, const float* __restrict__ Bm,
        float* __restrict__ hA, float* __restrict__ hB)
{
    extern __shared__ float sm[];
    float* d0 = sm;
    float* d1 = d0 + HELEMS;
    float* s0 = d1 + HELEMS;
    float* s1 = s0 + HELEMS;
    float* su = s1 + HELEMS;   // mu

    const int tid = threadIdx.x;
    const int b   = blockIdx.y;
    const int l0  = blockIdx.x * TL;

    // Load halo-extended tile (circular in L)
    for (int i = tid; i < HELEMS; i += 256) {
        int lr = i >> 6, c = i & 63;
        int l = (l0 - HALO + lr) & (LEN - 1);
        size_t g = ((size_t)b * LEN + l) * DD + c;
        float a = A[g], bb = Bm[g];
        d0[i] = a - bb;
        s0[i] = a + bb;
        su[i] = g_mu[g];
    }
    __syncthreads();

    float *dc = d0, *dn = d1, *sc = s0, *sn = s1;
#pragma unroll
    for (int k = 0; k < 6; k++) {
        for (int i = tid; i < HELEMS; i += 256) {
            int lr = i >> 6;
            if (lr >= 1 && lr < HTOT - 1) {
                // D' = smooth((1 - 2*eta*mu) * D), eta=0.15 -> factor (1-0.3*mu)
                float y0 = (1.f - 0.3f * su[i])      * dc[i];
                float ym = (1.f - 0.3f * su[i - DD]) * dc[i - DD];
                float yp = (1.f - 0.3f * su[i + DD]) * dc[i + DD];
                dn[i] = 0.9f * y0 + 0.05f * (ym + yp);
                sn[i] = 0.9f * sc[i] + 0.05f * (sc[i - DD] + sc[i + DD]);
            } else {
                dn[i] = dc[i];
                sn[i] = sc[i];
            }
        }
        __syncthreads();
        float* t;
        t = dc; dc = dn; dn = t;
        t = sc; sc = sn; sn = t;
    }

    // Output interior + energy partial
    float esum = 0.f;
    for (int i = tid; i < TL * DD; i += 256) {
        int r = i >> 6, c = i & 63;
        int li = (r + HALO) * DD + c;
        float Dv = dc[li], Sv = sc[li];
        size_t g = ((size_t)b * LEN + (l0 + r)) * DD + c;
        hA[g] = 0.5f * (Sv + Dv);
        hB[g] = 0.5f * (Sv - Dv);
        esum += 0.5f * su[li] * Dv * Dv;
    }

    // Block reduction (fixed order) -> partial
#pragma unroll
    for (int o = 16; o > 0; o >>= 1)
        esum += __shfl_xor_sync(0xffffffffu, esum, o);
    __shared__ float sred[8];
    if ((tid & 31) == 0) sred[tid >> 5] = esum;
    __syncthreads();
    if (tid == 0) {
        float t = 0.f;
#pragma unroll
        for (int w = 0; w < 8; w++) t += sred[w];
        g_epart[b * (LEN / TL) + blockIdx.x] = t;
    }
}

// ---------------------------------------------------------------------------
// Kernel 3: deterministic energy reduction: 128 partials -> energy[b]
// ---------------------------------------------------------------------------
__global__ void __launch_bounds__(128) energy_reduce(float* __restrict__ energy)
{
    const int b = blockIdx.x;
    const int tid = threadIdx.x;
    float v = g_epart[b * (LEN / TL) + tid];
#pragma unroll
    for (int o = 16; o > 0; o >>= 1)
        v += __shfl_xor_sync(0xffffffffu, v, o);
    __shared__ float s[4];
    if ((tid & 31) == 0) s[tid >> 5] = v;
    __syncthreads();
    if (tid == 0) energy[b] = s[0] + s[1] + s[2] + s[3];
}

// ---------------------------------------------------------------------------
extern "C" void kernel_launch(void* const* d_in, const int* in_sizes, int n_in,
                              void* d_out, int out_size)
{
    const float* A  = (const float*)d_in[0];
    const float* Bm = (const float*)d_in[1];
    const float* q  = (const float*)d_in[2];
    const float* W1 = (const float*)d_in[3];
    const float* b1 = (const float*)d_in[4];
    const float* W2 = (const float*)d_in[5];
    const float* b2 = (const float*)d_in[6];
    const float* Wq = (const float*)d_in[7];
    const float* bq = (const float*)d_in[8];

    float* out = (float*)d_out;
    float* hA = out;
    float* hB = out + (size_t)ROWS * DD;
    float* en = out + 2 * (size_t)ROWS * DD;

    const int smA = (TM * 128 + TM * 64 + TM * 256) * (int)sizeof(float); // 57344
    cudaFuncSetAttribute(mu_kernel, cudaFuncAttributeMaxDynamicSharedMemorySize, smA);
    mu_kernel<<<ROWS / TM, 256, smA>>>(A, Bm, q, W1, b1, W2, b2, Wq, bq);

    const int smB = 5 * HELEMS * (int)sizeof(float); // 97280
    cudaFuncSetAttribute(iter_kernel, cudaFuncAttributeMaxDynamicSharedMemorySize, smB);
    iter_kernel<<<dim3(LEN / TL, BSZ), 256, smB>>>(A, Bm, hA, hB);

    energy_reduce<<<BSZ, 128>>>(en);
}

// round 4
// speedup vs baseline: 1.0005x; 1.0005x over previous
#include <cuda_runtime.h>
#include <math.h>

// Problem shapes (fixed by the reference setup_inputs)
#define BSZ   32
#define LEN   8192
#define DD    64
#define HID   256
#define ROWS  (BSZ * LEN)          // 262144 rows of dim 64

// mu kernel tiling
#define TM    32                   // rows per block

// iteration kernel tiling
#define TL    64                   // L-rows per block (interior)
#define HALO  6                    // K iterations -> halo 6 each side
#define HTOT  (TL + 2*HALO)        // 76
#define HELEMS (HTOT * DD)         // 4864

// Scratch (device globals: no allocation allowed in kernel_launch)
__device__ float g_mu[(size_t)ROWS * DD];            // 64 MB
__device__ float g_epart[BSZ * (LEN / TL)];          // 32 x 128 partials

// ---------------------------------------------------------------------------
// Kernel 1: mu = softplus(relu([A;B]@W1+b1)@W2+b2) * (1 + 0.5*tanh(q@Wq+bq))
// Block: 256 threads, TM=32 rows. Stage 1: each thread owns one hidden column
// (j = tid) and accumulates all 32 rows in registers (x broadcast from smem,
// W1 row coalesced from L2). Stage 2/3: thread owns (out col j2 = tid&63,
// row group tid>>6 of 8 rows).
// ---------------------------------------------------------------------------
__global__ void __launch_bounds__(256) mu_kernel(
        const float* __restrict__ A,  const float* __restrict__ Bm,
        const float* __restrict__ q,
        const float* __restrict__ W1, const float* __restrict__ b1,
        const float* __restrict__ W2, const float* __restrict__ b2,
        const float* __restrict__ Wq, const float* __restrict__ bq)
{
    extern __shared__ float sm[];
    float* sx  = sm;                    // [TM][128]  concat(A,B)
    float* sq  = sx + TM * 128;         // [TM][64]
    float* sh1 = sq + TM * 64;          // [TM][256]  relu hidden

    const int tid = threadIdx.x;
    const size_t row0 = (size_t)blockIdx.x * TM;

    // Load inputs for this row tile
    for (int i = tid; i < TM * DD; i += 256) {
        int r = i >> 6, c = i & 63;
        size_t g = (row0 + r) * DD + c;
        sx[r * 128 + c]      = A[g];
        sx[r * 128 + 64 + c] = Bm[g];
        sq[r * 64 + c]       = q[g];
    }
    __syncthreads();

    // Stage 1: hidden layer. j = tid in [0,256)
    {
        float acc[TM];
#pragma unroll
        for (int r = 0; r < TM; r++) acc[r] = 0.f;
        const int j = tid;
#pragma unroll 4
        for (int k = 0; k < 128; k++) {
            float w = W1[k * HID + j];
#pragma unroll
            for (int r = 0; r < TM; r++) acc[r] += sx[r * 128 + k] * w;
        }
        float bb = b1[j];
#pragma unroll
        for (int r = 0; r < TM; r++) sh1[r * HID + j] = fmaxf(acc[r] + bb, 0.f);
    }
    __syncthreads();

    // Stage 2: mu_pre = h1 @ W2 + b2 ; Stage 3: gate = tanh(q @ Wq + bq)
    const int j2 = tid & 63;      // output column
    const int rg = tid >> 6;      // row group 0..3, rows rg*8 .. rg*8+7

    float acc2[8];
#pragma unroll
    for (int r = 0; r < 8; r++) acc2[r] = 0.f;
#pragma unroll 4
    for (int k = 0; k < HID; k++) {
        float w = W2[k * DD + j2];
#pragma unroll
        for (int r = 0; r < 8; r++) acc2[r] += sh1[(rg * 8 + r) * HID + k] * w;
    }

    float acc3[8];
#pragma unroll
    for (int r = 0; r < 8; r++) acc3[r] = 0.f;
#pragma unroll 4
    for (int k = 0; k < DD; k++) {
        float w = Wq[k * DD + j2];
#pragma unroll
        for (int r = 0; r < 8; r++) acc3[r] += sq[(rg * 8 + r) * DD + k] * w;
    }

    const float b2v = b2[j2], bqv = bq[j2];
#pragma unroll
    for (int r = 0; r < 8; r++) {
        float m = acc2[r] + b2v;
        m = (m > 20.f) ? m : log1pf(expf(m));      // softplus
        float g = tanhf(acc3[r] + bqv);
        g_mu[(row0 + rg * 8 + r) * DD + j2] = m * (1.f + 0.5f * g);
    }
}

// ---------------------------------------------------------------------------
// Kernel 2: K=6 fused iterations on D = A-B (with pointwise (1-0.3*mu) scale)
// and S = A+B (pure stencil), tile of TL L-rows with halo 6, circular in L.
// Writes hA, hB; per-block energy partial (deterministic).
// smooth(x)[l] = 0.9*x[l] + 0.05*(x[l-1] + x[l+1])
// ---------------------------------------------------------------------------
__global__ void __launch_bounds__(256) iter_kernel(
        const float* __restrict__ A, const float* __restrict__ Bm,
        float* __restrict__ hA, float* __restrict__ hB)
{
    extern __shared__ float sm[];
    float* d0 = sm;
    float* d1 = d0 + HELEMS;
    float* s0 = d1 + HELEMS;
    float* s1 = s0 + HELEMS;
    float* su = s1 + HELEMS;   // mu

    const int tid = threadIdx.x;
    const int b   = blockIdx.y;
    const int l0  = blockIdx.x * TL;

    // Load halo-extended tile (circular in L)
    for (int i = tid; i < HELEMS; i += 256) {
        int lr = i >> 6, c = i & 63;
        int l = (l0 - HALO + lr) & (LEN - 1);
        size_t g = ((size_t)b * LEN + l) * DD + c;
        float a = A[g], bb = Bm[g];
        d0[i] = a - bb;
        s0[i] = a + bb;
        su[i] = g_mu[g];
    }
    __syncthreads();

    float *dc = d0, *dn = d1, *sc = s0, *sn = s1;
#pragma unroll
    for (int k = 0; k < 6; k++) {
        for (int i = tid; i < HELEMS; i += 256) {
            int lr = i >> 6;
            if (lr >= 1 && lr < HTOT - 1) {
                // D' = smooth((1 - 2*eta*mu) * D), eta=0.15 -> factor (1-0.3*mu)
                float y0 = (1.f - 0.3f * su[i])      * dc[i];
                float ym = (1.f - 0.3f * su[i - DD]) * dc[i - DD];
                float yp = (1.f - 0.3f * su[i + DD]) * dc[i + DD];
                dn[i] = 0.9f * y0 + 0.05f * (ym + yp);
                sn[i] = 0.9f * sc[i] + 0.05f * (sc[i - DD] + sc[i + DD]);
            } else {
                dn[i] = dc[i];
                sn[i] = sc[i];
            }
        }
        __syncthreads();
        float* t;
        t = dc; dc = dn; dn = t;
        t = sc; sc = sn; sn = t;
    }

    // Output interior + energy partial
    float esum = 0.f;
    for (int i = tid; i < TL * DD; i += 256) {
        int r = i >> 6, c = i & 63;
        int li = (r + HALO) * DD + c;
        float Dv = dc[li], Sv = sc[li];
        size_t g = ((size_t)b * LEN + (l0 + r)) * DD + c;
        hA[g] = 0.5f * (Sv + Dv);
        hB[g] = 0.5f * (Sv - Dv);
        esum += 0.5f * su[li] * Dv * Dv;
    }

    // Block reduction (fixed order) -> partial
#pragma unroll
    for (int o = 16; o > 0; o >>= 1)
        esum += __shfl_xor_sync(0xffffffffu, esum, o);
    __shared__ float sred[8];
    if ((tid & 31) == 0) sred[tid >> 5] = esum;
    __syncthreads();
    if (tid == 0) {
        float t = 0.f;
#pragma unroll
        for (int w = 0; w < 8; w++) t += sred[w];
        g_epart[b * (LEN / TL) + blockIdx.x] = t;
    }
}

// ---------------------------------------------------------------------------
// Kernel 3: deterministic energy reduction: 128 partials -> energy[b]
// ---------------------------------------------------------------------------
__global__ void __launch_bounds__(128) energy_reduce(float* __restrict__ energy)
{
    const int b = blockIdx.x;
    const int tid = threadIdx.x;
    float v = g_epart[b * (LEN / TL) + tid];
#pragma unroll
    for (int o = 16; o > 0; o >>= 1)
        v += __shfl_xor_sync(0xffffffffu, v, o);
    __shared__ float s[4];
    if ((tid & 31) == 0) s[tid >> 5] = v;
    __syncthreads();
    if (tid == 0) energy[b] = s[0] + s[1] + s[2] + s[3];
}

// ---------------------------------------------------------------------------
extern "C" void kernel_launch(void* const* d_in, const int* in_sizes, int n_in,
                              void* d_out, int out_size)
{
    const float* A  = (const float*)d_in[0];
    const float* Bm = (const float*)d_in[1];
    const float* q  = (const float*)d_in[2];
    const float* W1 = (const float*)d_in[3];
    const float* b1 = (const float*)d_in[4];
    const float* W2 = (const float*)d_in[5];
    const float* b2 = (const float*)d_in[6];
    const float* Wq = (const float*)d_in[7];
    const float* bq = (const float*)d_in[8];

    float* out = (float*)d_out;
    float* hA = out;
    float* hB = out + (size_t)ROWS * DD;
    float* en = out + 2 * (size_t)ROWS * DD;

    const int smA = (TM * 128 + TM * 64 + TM * 256) * (int)sizeof(float); // 57344
    cudaFuncSetAttribute(mu_kernel, cudaFuncAttributeMaxDynamicSharedMemorySize, smA);
    mu_kernel<<<ROWS / TM, 256, smA>>>(A, Bm, q, W1, b1, W2, b2, Wq, bq);

    const int smB = 5 * HELEMS * (int)sizeof(float); // 97280
    cudaFuncSetAttribute(iter_kernel, cudaFuncAttributeMaxDynamicSharedMemorySize, smB);
    iter_kernel<<<dim3(LEN / TL, BSZ), 256, smB>>>(A, Bm, hA, hB);

    energy_reduce<<<BSZ, 128>>>(en);
}

// round 5
// speedup vs baseline: 2.2158x; 2.2147x over previous
#include <cuda_runtime.h>
#include <cuda_bf16.h>
#include <math.h>

#define BSZ 32
#define LEN 8192
#define DD  64
#define HID 256
#define ROWS (BSZ*LEN)

// bf16-element strides: (stride mod 32 words)==4 -> conflict-free frag loads
#define XS  136
#define W1S 136
#define W2S 264
#define WQS 72
#define QS  72
#define PS  68   // fp32 words

// smem byte offsets
#define OFF_XHI  0
#define OFF_XLO  17408
#define OFF_QHI  0
#define OFF_QLO  9216
#define OFF_W1HI 34816
#define OFF_W1LO 104448
#define OFF_W2HI 34816
#define OFF_W2LO 68608
#define OFF_WQHI 102400
#define OFF_WQLO 111616
#define OFF_PMU  174080
#define OFF_PG   191488
#define SMEM_MU  208896

__device__ __align__(16) __nv_bfloat16 g_W1T[2][256][W1S];
__device__ __align__(16) __nv_bfloat16 g_W2T[2][64][W2S];
__device__ __align__(16) __nv_bfloat16 g_WqT[2][64][WQS];
__device__ float g_mu[(size_t)ROWS * DD];
__device__ float g_epart[BSZ * 64];

// ---------------------------------------------------------------------------
__global__ void __launch_bounds__(256) prep_kernel(
        const float* __restrict__ W1, const float* __restrict__ W2,
        const float* __restrict__ Wq)
{
    int i = blockIdx.x * blockDim.x + threadIdx.x;
    if (i < 128 * 256) {
        int k = i >> 8, n = i & 255;
        float w = W1[i];
        __nv_bfloat16 h = __float2bfloat16(w);
        g_W1T[0][n][k] = h;
        g_W1T[1][n][k] = __float2bfloat16(w - __bfloat162float(h));
    }
    if (i < 256 * 64) {
        int k = i >> 6, n = i & 63;
        float w = W2[i];
        __nv_bfloat16 h = __float2bfloat16(w);
        g_W2T[0][n][k] = h;
        g_W2T[1][n][k] = __float2bfloat16(w - __bfloat162float(h));
    }
    if (i < 64 * 64) {
        int k = i >> 6, n = i & 63;
        float w = Wq[i];
        __nv_bfloat16 h = __float2bfloat16(w);
        g_WqT[0][n][k] = h;
        g_WqT[1][n][k] = __float2bfloat16(w - __bfloat162float(h));
    }
}

__device__ __forceinline__ void mma16816(float* c, const unsigned* a,
                                         unsigned b0, unsigned b1)
{
    asm volatile(
        "mma.sync.aligned.m16n8k16.row.col.f32.bf16.bf16.f32 "
        "{%0,%1,%2,%3},{%4,%5,%6,%7},{%8,%9},{%0,%1,%2,%3};\n"
        : "+f"(c[0]), "+f"(c[1]), "+f"(c[2]), "+f"(c[3])
        : "r"(a[0]), "r"(a[1]), "r"(a[2]), "r"(a[3]), "r"(b0), "r"(b1));
}

__device__ __forceinline__ void splitpack(float x, float y, unsigned& hp, unsigned& lp)
{
    x = fmaxf(x, 0.f); y = fmaxf(y, 0.f);   // fused ReLU
    __nv_bfloat16 xh = __float2bfloat16(x), yh = __float2bfloat16(y);
    float xl = x - __bfloat162float(xh), yl = y - __bfloat162float(yh);
    hp = (unsigned)__bfloat16_as_ushort(xh) | ((unsigned)__bfloat16_as_ushort(yh) << 16);
    lp = (unsigned)__bfloat16_as_ushort(__float2bfloat16(xl)) |
         ((unsigned)__bfloat16_as_ushort(__float2bfloat16(yl)) << 16);
}

// ---------------------------------------------------------------------------
// mu kernel: 64 rows/block, 8 warps = 2(m32) x 4(n64). Tensor-core MLP,
// bf16 3-term split; H stays in registers (C-frag -> A-frag repack).
// ---------------------------------------------------------------------------
__global__ void __launch_bounds__(256) mu_kernel(
        const float* __restrict__ A, const float* __restrict__ Bm,
        const float* __restrict__ q,
        const float* __restrict__ b1, const float* __restrict__ b2,
        const float* __restrict__ bq)
{
    extern __shared__ char sm[];
    const int tid  = threadIdx.x;
    const int lane = tid & 31;
    const int wid  = tid >> 5;
    const int wm   = wid & 1;
    const int wn   = wid >> 1;
    const int r    = lane >> 2;
    const int c2   = lane & 3;
    const size_t row0 = (size_t)blockIdx.x * 64;

    __nv_bfloat16* sXhi = (__nv_bfloat16*)(sm + OFF_XHI);
    __nv_bfloat16* sXlo = (__nv_bfloat16*)(sm + OFF_XLO);

    for (int i = tid; i < 64 * 128; i += 256) {
        int rr = i >> 7, c = i & 127;
        float v = (c < 64) ? A[(row0 + rr) * 64 + c] : Bm[(row0 + rr) * 64 + (c - 64)];
        __nv_bfloat16 h = __float2bfloat16(v);
        sXhi[rr * XS + c] = h;
        sXlo[rr * XS + c] = __float2bfloat16(v - __bfloat162float(h));
    }
    {
        const uint4* src = (const uint4*)(&g_W1T[0][0][0]);
        uint4* dst = (uint4*)(sm + OFF_W1HI);
        for (int i = tid; i < 8704; i += 256) dst[i] = src[i];
    }
    __syncthreads();

    // -------- Stage 1: H = relu(X @ W1 + b1), acc in C-frags --------
    float acc[2][8][4];
#pragma unroll
    for (int nt = 0; nt < 8; nt++) {
        float bv0 = b1[wn * 64 + nt * 8 + 2 * c2];
        float bv1 = b1[wn * 64 + nt * 8 + 2 * c2 + 1];
#pragma unroll
        for (int mt = 0; mt < 2; mt++) {
            acc[mt][nt][0] = bv0; acc[mt][nt][1] = bv1;
            acc[mt][nt][2] = bv0; acc[mt][nt][3] = bv1;
        }
    }
    const __nv_bfloat16* sW1hi = (const __nv_bfloat16*)(sm + OFF_W1HI);
    const __nv_bfloat16* sW1lo = (const __nv_bfloat16*)(sm + OFF_W1LO);
#pragma unroll
    for (int ks = 0; ks < 8; ks++) {
        const int k0 = ks * 16;
        unsigned ah[2][4], al[2][4];
#pragma unroll
        for (int mt = 0; mt < 2; mt++) {
            int row = wm * 32 + mt * 16 + r;
            ah[mt][0] = *(const unsigned*)(sXhi + row * XS + k0 + 2 * c2);
            ah[mt][1] = *(const unsigned*)(sXhi + (row + 8) * XS + k0 + 2 * c2);
            ah[mt][2] = *(const unsigned*)(sXhi + row * XS + k0 + 8 + 2 * c2);
            ah[mt][3] = *(const unsigned*)(sXhi + (row + 8) * XS + k0 + 8 + 2 * c2);
            al[mt][0] = *(const unsigned*)(sXlo + row * XS + k0 + 2 * c2);
            al[mt][1] = *(const unsigned*)(sXlo + (row + 8) * XS + k0 + 2 * c2);
            al[mt][2] = *(const unsigned*)(sXlo + row * XS + k0 + 8 + 2 * c2);
            al[mt][3] = *(const unsigned*)(sXlo + (row + 8) * XS + k0 + 8 + 2 * c2);
        }
#pragma unroll
        for (int nt = 0; nt < 8; nt++) {
            int n = wn * 64 + nt * 8 + r;
            unsigned bh0 = *(const unsigned*)(sW1hi + n * W1S + k0 + 2 * c2);
            unsigned bh1 = *(const unsigned*)(sW1hi + n * W1S + k0 + 8 + 2 * c2);
            unsigned bl0 = *(const unsigned*)(sW1lo + n * W1S + k0 + 2 * c2);
            unsigned bl1 = *(const unsigned*)(sW1lo + n * W1S + k0 + 8 + 2 * c2);
#pragma unroll
            for (int mt = 0; mt < 2; mt++) {
                mma16816(acc[mt][nt], ah[mt], bh0, bh1);
                mma16816(acc[mt][nt], ah[mt], bl0, bl1);
                mma16816(acc[mt][nt], al[mt], bh0, bh1);
            }
        }
    }

    // Repack relu'd C-frags into stage-2 A-frags (registers only)
    unsigned Ah[2][4][4], Al[2][4][4];
#pragma unroll
    for (int mt = 0; mt < 2; mt++)
#pragma unroll
        for (int t = 0; t < 4; t++) {
            splitpack(acc[mt][2*t][0],   acc[mt][2*t][1],   Ah[mt][t][0], Al[mt][t][0]);
            splitpack(acc[mt][2*t][2],   acc[mt][2*t][3],   Ah[mt][t][1], Al[mt][t][1]);
            splitpack(acc[mt][2*t+1][0], acc[mt][2*t+1][1], Ah[mt][t][2], Al[mt][t][2]);
            splitpack(acc[mt][2*t+1][2], acc[mt][2*t+1][3], Ah[mt][t][3], Al[mt][t][3]);
        }

    __syncthreads();   // X + W1 regions now dead

    // -------- Phase-2 smem loads: q, W2T, WqT --------
    __nv_bfloat16* sQhi = (__nv_bfloat16*)(sm + OFF_QHI);
    __nv_bfloat16* sQlo = (__nv_bfloat16*)(sm + OFF_QLO);
    for (int i = tid; i < 64 * 64; i += 256) {
        int rr = i >> 6, c = i & 63;
        float v = q[(row0 + rr) * 64 + c];
        __nv_bfloat16 h = __float2bfloat16(v);
        sQhi[rr * QS + c] = h;
        sQlo[rr * QS + c] = __float2bfloat16(v - __bfloat162float(h));
    }
    {
        const uint4* s2 = (const uint4*)(&g_W2T[0][0][0]);
        uint4* d2 = (uint4*)(sm + OFF_W2HI);
        for (int i = tid; i < 4224; i += 256) d2[i] = s2[i];
        const uint4* s3 = (const uint4*)(&g_WqT[0][0][0]);
        uint4* d3 = (uint4*)(sm + OFF_WQHI);
        for (int i = tid; i < 1152; i += 256) d3[i] = s3[i];
    }
    __syncthreads();

    float* sPmu = (float*)(sm + OFF_PMU);
    float* sPg  = (float*)(sm + OFF_PG);

    // -------- Gate partial: q(k16 slice per n-warp) @ Wq --------
    {
        const __nv_bfloat16* sWqhi = (const __nv_bfloat16*)(sm + OFF_WQHI);
        const __nv_bfloat16* sWqlo = (const __nv_bfloat16*)(sm + OFF_WQLO);
        float accg[2][8][4];
#pragma unroll
        for (int mt = 0; mt < 2; mt++)
#pragma unroll
            for (int nt = 0; nt < 8; nt++)
#pragma unroll
                for (int i = 0; i < 4; i++) accg[mt][nt][i] = 0.f;
        const int kb = wn * 16;
        unsigned qh[2][4], ql[2][4];
#pragma unroll
        for (int mt = 0; mt < 2; mt++) {
            int row = wm * 32 + mt * 16 + r;
            qh[mt][0] = *(const unsigned*)(sQhi + row * QS + kb + 2 * c2);
            qh[mt][1] = *(const unsigned*)(sQhi + (row + 8) * QS + kb + 2 * c2);
            qh[mt][2] = *(const unsigned*)(sQhi + row * QS + kb + 8 + 2 * c2);
            qh[mt][3] = *(const unsigned*)(sQhi + (row + 8) * QS + kb + 8 + 2 * c2);
            ql[mt][0] = *(const unsigned*)(sQlo + row * QS + kb + 2 * c2);
            ql[mt][1] = *(const unsigned*)(sQlo + (row + 8) * QS + kb + 2 * c2);
            ql[mt][2] = *(const unsigned*)(sQlo + row * QS + kb + 8 + 2 * c2);
            ql[mt][3] = *(const unsigned*)(sQlo + (row + 8) * QS + kb + 8 + 2 * c2);
        }
#pragma unroll
        for (int nt = 0; nt < 8; nt++) {
            int n = nt * 8 + r;
            unsigned bh0 = *(const unsigned*)(sWqhi + n * WQS + kb + 2 * c2);
            unsigned bh1 = *(const unsigned*)(sWqhi + n * WQS + kb + 8 + 2 * c2);
            unsigned bl0 = *(const unsigned*)(sWqlo + n * WQS + kb + 2 * c2);
            unsigned bl1 = *(const unsigned*)(sWqlo + n * WQS + kb + 8 + 2 * c2);
#pragma unroll
            for (int mt = 0; mt < 2; mt++) {
                mma16816(accg[mt][nt], qh[mt], bh0, bh1);
                mma16816(accg[mt][nt], qh[mt], bl0, bl1);
                mma16816(accg[mt][nt], ql[mt], bh0, bh1);
            }
        }
        // deterministic 4-round reduction into sPg
        for (int rnd = 0; rnd < 4; rnd++) {
            if (wn == rnd) {
#pragma unroll
                for (int mt = 0; mt < 2; mt++)
#pragma unroll
                    for (int nt = 0; nt < 8; nt++) {
                        int rowp = wm * 32 + mt * 16 + r;
                        int col  = nt * 8 + 2 * c2;
                        if (rnd == 0) {
                            sPg[rowp*PS + col]       = accg[mt][nt][0];
                            sPg[rowp*PS + col+1]     = accg[mt][nt][1];
                            sPg[(rowp+8)*PS + col]   = accg[mt][nt][2];
                            sPg[(rowp+8)*PS + col+1] = accg[mt][nt][3];
                        } else {
                            sPg[rowp*PS + col]       += accg[mt][nt][0];
                            sPg[rowp*PS + col+1]     += accg[mt][nt][1];
                            sPg[(rowp+8)*PS + col]   += accg[mt][nt][2];
                            sPg[(rowp+8)*PS + col+1] += accg[mt][nt][3];
                        }
                    }
            }
            __syncthreads();
        }
    }

    // -------- Stage 2 partial: H(k64 slice per n-warp) @ W2 --------
    {
        const __nv_bfloat16* sW2hi = (const __nv_bfloat16*)(sm + OFF_W2HI);
        const __nv_bfloat16* sW2lo = (const __nv_bfloat16*)(sm + OFF_W2LO);
        float acc2[2][8][4];
#pragma unroll
        for (int mt = 0; mt < 2; mt++)
#pragma unroll
            for (int nt = 0; nt < 8; nt++)
#pragma unroll
                for (int i = 0; i < 4; i++) acc2[mt][nt][i] = 0.f;
#pragma unroll
        for (int t = 0; t < 4; t++) {
            const int kb = wn * 64 + t * 16;
#pragma unroll
            for (int nt = 0; nt < 8; nt++) {
                int n = nt * 8 + r;
                unsigned bh0 = *(const unsigned*)(sW2hi + n * W2S + kb + 2 * c2);
                unsigned bh1 = *(const unsigned*)(sW2hi + n * W2S + kb + 8 + 2 * c2);
                unsigned bl0 = *(const unsigned*)(sW2lo + n * W2S + kb + 2 * c2);
                unsigned bl1 = *(const unsigned*)(sW2lo + n * W2S + kb + 8 + 2 * c2);
#pragma unroll
                for (int mt = 0; mt < 2; mt++) {
                    mma16816(acc2[mt][nt], Ah[mt][t], bh0, bh1);
                    mma16816(acc2[mt][nt], Ah[mt][t], bl0, bl1);
                    mma16816(acc2[mt][nt], Al[mt][t], bh0, bh1);
                }
            }
        }
        for (int rnd = 0; rnd < 4; rnd++) {
            if (wn == rnd) {
#pragma unroll
                for (int mt = 0; mt < 2; mt++)
#pragma unroll
                    for (int nt = 0; nt < 8; nt++) {
                        int rowp = wm * 32 + mt * 16 + r;
                        int col  = nt * 8 + 2 * c2;
                        if (rnd == 0) {
                            sPmu[rowp*PS + col]       = acc2[mt][nt][0];
                            sPmu[rowp*PS + col+1]     = acc2[mt][nt][1];
                            sPmu[(rowp+8)*PS + col]   = acc2[mt][nt][2];
                            sPmu[(rowp+8)*PS + col+1] = acc2[mt][nt][3];
                        } else {
                            sPmu[rowp*PS + col]       += acc2[mt][nt][0];
                            sPmu[rowp*PS + col+1]     += acc2[mt][nt][1];
                            sPmu[(rowp+8)*PS + col]   += acc2[mt][nt][2];
                            sPmu[(rowp+8)*PS + col+1] += acc2[mt][nt][3];
                        }
                    }
            }
            __syncthreads();
        }
    }

    // -------- Epilogue: mu = softplus(M+b2) * (1 + 0.5*tanh(G+bq)) --------
    for (int i = tid; i < 64 * 64; i += 256) {
        int rr = i >> 6, c = i & 63;
        float m = sPmu[rr * PS + c] + b2[c];
        float sp = fmaxf(m, 0.f) + log1pf(expf(-fabsf(m)));
        float g = tanhf(sPg[rr * PS + c] + bq[c]);
        g_mu[(row0 + rr) * 64 + c] = sp * (1.f + 0.5f * g);
    }
}

// ---------------------------------------------------------------------------
// Iteration kernel: register-resident stencil, 18 rows/thread, edge-only
// smem exchange (double-buffered). 128 interior L-rows per block, halo 8.
// smooth(x)[l] = 0.9*x[l] + 0.05*(x[l-1]+x[l+1]);  D scaled by (1-0.3*mu).
// ---------------------------------------------------------------------------
__global__ void __launch_bounds__(512) iter_kernel(
        const float* __restrict__ A, const float* __restrict__ Bm,
        float* __restrict__ hA, float* __restrict__ hB)
{
    __shared__ float sme[2][4][8][64];
    const int tid = threadIdx.x;
    const int c = tid & 63;
    const int j = tid >> 6;             // chunk 0..7
    const int b = blockIdx.y;
    const int lbase = blockIdx.x * 128 - 8;
    const size_t base = ((size_t)b << 13);

    float D[18], S[18], MU[18];
#pragma unroll
    for (int rr = 0; rr < 18; rr++) {
        int l = (lbase + j * 18 + rr) & (LEN - 1);
        size_t g = (base + l) * 64 + c;
        float a = A[g], bb = Bm[g];
        D[rr] = a - bb;
        S[rr] = a + bb;
        MU[rr] = g_mu[g];
    }

#pragma unroll
    for (int k = 0; k < 6; k++) {
        const int p = k & 1;
        sme[p][0][j][c] = (1.f - 0.3f * MU[0])  * D[0];
        sme[p][1][j][c] = (1.f - 0.3f * MU[17]) * D[17];
        sme[p][2][j][c] = S[0];
        sme[p][3][j][c] = S[17];
        __syncthreads();
        float gylo = (j > 0) ? sme[p][1][j - 1][c] : 0.f;
        float gyhi = (j < 7) ? sme[p][0][j + 1][c] : 0.f;
        float gslo = (j > 0) ? sme[p][3][j - 1][c] : 0.f;
        float gshi = (j < 7) ? sme[p][2][j + 1][c] : 0.f;

        float yprev = gylo, sprev = gslo;
#pragma unroll
        for (int rr = 0; rr < 18; rr++) {
            float ycur  = (1.f - 0.3f * MU[rr]) * D[rr];
            float ynext = (rr < 17) ? (1.f - 0.3f * MU[rr + 1]) * D[rr + 1] : gyhi;
            float scur  = S[rr];
            float snext = (rr < 17) ? S[rr + 1] : gshi;
            D[rr] = 0.9f * ycur + 0.05f * (yprev + ynext);
            S[rr] = 0.9f * scur + 0.05f * (sprev + snext);
            yprev = ycur;
            sprev = scur;
        }
    }

    float esum = 0.f;
#pragma unroll
    for (int rr = 0; rr < 18; rr++) {
        int gidx = j * 18 + rr;
        if (gidx >= 8 && gidx < 136) {
            int l = blockIdx.x * 128 + (gidx - 8);
            size_t g = (base + l) * 64 + c;
            hA[g] = 0.5f * (S[rr] + D[rr]);
            hB[g] = 0.5f * (S[rr] - D[rr]);
            esum += 0.5f * MU[rr] * D[rr] * D[rr];
        }
    }

#pragma unroll
    for (int o = 16; o > 0; o >>= 1)
        esum += __shfl_xor_sync(0xffffffffu, esum, o);
    __shared__ float sred[16];
    if ((tid & 31) == 0) sred[tid >> 5] = esum;
    __syncthreads();
    if (tid == 0) {
        float t = 0.f;
#pragma unroll
        for (int w = 0; w < 16; w++) t += sred[w];
        g_epart[b * 64 + blockIdx.x] = t;
    }
}

// ---------------------------------------------------------------------------
__global__ void __launch_bounds__(64) energy_reduce(float* __restrict__ energy)
{
    const int b = blockIdx.x;
    const int tid = threadIdx.x;
    float v = g_epart[b * 64 + tid];
#pragma unroll
    for (int o = 16; o > 0; o >>= 1)
        v += __shfl_xor_sync(0xffffffffu, v, o);
    __shared__ float s[2];
    if ((tid & 31) == 0) s[tid >> 5] = v;
    __syncthreads();
    if (tid == 0) energy[b] = s[0] + s[1];
}

// ---------------------------------------------------------------------------
extern "C" void kernel_launch(void* const* d_in, const int* in_sizes, int n_in,
                              void* d_out, int out_size)
{
    const float* A  = (const float*)d_in[0];
    const float* Bm = (const float*)d_in[1];
    const float* q  = (const float*)d_in[2];
    const float* W1 = (const float*)d_in[3];
    const float* b1 = (const float*)d_in[4];
    const float* W2 = (const float*)d_in[5];
    const float* b2 = (const float*)d_in[6];
    const float* Wq = (const float*)d_in[7];
    const float* bq = (const float*)d_in[8];

    float* out = (float*)d_out;
    float* hA = out;
    float* hB = out + (size_t)ROWS * DD;
    float* en = out + 2 * (size_t)ROWS * DD;

    prep_kernel<<<128, 256>>>(W1, W2, Wq);

    static int attr_set = 0;
    if (!attr_set) {
        cudaFuncSetAttribute(mu_kernel,
            cudaFuncAttributeMaxDynamicSharedMemorySize, SMEM_MU);
        attr_set = 1;
    }
    mu_kernel<<<ROWS / 64, 256, SMEM_MU>>>(A, Bm, q, b1, b2, bq);

    iter_kernel<<<dim3(LEN / 128, BSZ), 512>>>(A, Bm, hA, hB);

    energy_reduce<<<BSZ, 64>>>(en);
}

// round 6
// speedup vs baseline: 3.3212x; 1.4989x over previous
#include <cuda_runtime.h>
#include <cuda_bf16.h>
#include <math.h>

#define BSZ 32
#define LEN 8192
#define DD  64
#define HID 256
#define ROWS (BSZ*LEN)

#define W1S 132            // bf16 elems per W1/X row (128 + 4 pad)
#define W2S 260            // bf16 elems per W2 row (256 + 4 pad)
#define TROWS 32           // rows per mu tile
#define NTILES (ROWS/TROWS) // 8192
#define MUGRID 148

// smem byte offsets (mu kernel)
#define SZ_W1H (256*W1S*2)            // 67584
#define OFF_W2 (2*SZ_W1H)             // 135168
#define SZ_W2H (64*W2S*2)             // 33280
#define OFF_X  (OFF_W2 + 2*SZ_W2H)    // 201728
#define SZ_XH  (TROWS*W1S*2)          // 8448
#define SMEM_MU (OFF_X + 2*SZ_XH)     // 218624

__device__ __align__(16) __nv_bfloat16 g_W1T[2][256][W1S];
__device__ __align__(16) __nv_bfloat16 g_W2T[2][64][W2S];
__device__ float g_mu[(size_t)ROWS * DD];
__device__ float g_gf[(size_t)ROWS * DD];
__device__ float g_epart[BSZ * 64];

// ---------------------------------------------------------------------------
__global__ void __launch_bounds__(256) prep_kernel(
        const float* __restrict__ W1, const float* __restrict__ W2)
{
    int i = blockIdx.x * blockDim.x + threadIdx.x;
    if (i < 128 * 256) {
        int k = i >> 8, n = i & 255;
        float w = W1[i];
        __nv_bfloat16 h = __float2bfloat16(w);
        g_W1T[0][n][k] = h;
        g_W1T[1][n][k] = __float2bfloat16(w - __bfloat162float(h));
    }
    if (i < 256 * 64) {
        int k = i >> 6, n = i & 63;
        float w = W2[i];
        __nv_bfloat16 h = __float2bfloat16(w);
        g_W2T[0][n][k] = h;
        g_W2T[1][n][k] = __float2bfloat16(w - __bfloat162float(h));
    }
}

// ---------------------------------------------------------------------------
// gate kernel: g_gf = 1 + 0.5*tanh(q @ Wq + bq), fp32 scalar (exact)
// ---------------------------------------------------------------------------
__global__ void __launch_bounds__(256) gate_kernel(
        const float* __restrict__ q, const float* __restrict__ Wq,
        const float* __restrict__ bq)
{
    __shared__ float sq[64 * 65];
    __shared__ float sw[64 * 65];
    const int tid = threadIdx.x;
    const size_t row0 = (size_t)blockIdx.x * 64;
    for (int i = tid; i < 64 * 64; i += 256) {
        int r = i >> 6, c = i & 63;
        sq[r * 65 + c] = q[(row0 + r) * 64 + c];
        sw[r * 65 + c] = Wq[i];              // sw[k][n]
    }
    __syncthreads();
    const int col = tid & 63, rg = tid >> 6;
    float acc[16];
#pragma unroll
    for (int i = 0; i < 16; i++) acc[i] = 0.f;
#pragma unroll 4
    for (int k = 0; k < 64; k++) {
        float w = sw[k * 65 + col];
#pragma unroll
        for (int i = 0; i < 16; i++) acc[i] += sq[(rg * 16 + i) * 65 + k] * w;
    }
    const float bqv = bq[col];
#pragma unroll
    for (int i = 0; i < 16; i++)
        g_gf[(row0 + rg * 16 + i) * 64 + col] = 1.f + 0.5f * tanhf(acc[i] + bqv);
}

// ---------------------------------------------------------------------------
__device__ __forceinline__ void mma16816(float* c, const unsigned* a,
                                         unsigned b0, unsigned b1)
{
    asm volatile(
        "mma.sync.aligned.m16n8k16.row.col.f32.bf16.bf16.f32 "
        "{%0,%1,%2,%3},{%4,%5,%6,%7},{%8,%9},{%0,%1,%2,%3};\n"
        : "+f"(c[0]), "+f"(c[1]), "+f"(c[2]), "+f"(c[3])
        : "r"(a[0]), "r"(a[1]), "r"(a[2]), "r"(a[3]), "r"(b0), "r"(b1));
}

__device__ __forceinline__ void splitpack(float x, float y, unsigned& hp, unsigned& lp)
{
    x = fmaxf(x, 0.f); y = fmaxf(y, 0.f);   // fused ReLU
    __nv_bfloat16 xh = __float2bfloat16(x), yh = __float2bfloat16(y);
    float xl = x - __bfloat162float(xh), yl = y - __bfloat162float(yh);
    hp = (unsigned)__bfloat16_as_ushort(xh) | ((unsigned)__bfloat16_as_ushort(yh) << 16);
    lp = (unsigned)__bfloat16_as_ushort(__float2bfloat16(xl)) |
         ((unsigned)__bfloat16_as_ushort(__float2bfloat16(yl)) << 16);
}

__device__ __forceinline__ float softplusf(float m)
{
    return fmaxf(m, 0.f) + log1pf(expf(-fabsf(m)));
}

// ---------------------------------------------------------------------------
// Persistent mu kernel: weights resident in smem, loop over 32-row tiles.
// 8 warps, each owns 32 hidden cols (stage1) / 8 out cols (stage2), m=32.
// H restaged through the X smem buffer in two k-half panels.
// ---------------------------------------------------------------------------
__global__ void __launch_bounds__(256, 1) mu_kernel(
        const float* __restrict__ A, const float* __restrict__ Bm,
        const float* __restrict__ b1, const float* __restrict__ b2)
{
    extern __shared__ char sm[];
    __nv_bfloat16* sW1hi = (__nv_bfloat16*)(sm);
    __nv_bfloat16* sW1lo = sW1hi + 256 * W1S;
    __nv_bfloat16* sW2hi = (__nv_bfloat16*)(sm + OFF_W2);
    __nv_bfloat16* sW2lo = sW2hi + 64 * W2S;
    __nv_bfloat16* sXhi  = (__nv_bfloat16*)(sm + OFF_X);   // reused for H
    __nv_bfloat16* sXlo  = sXhi + TROWS * W1S;

    const int tid = threadIdx.x, lane = tid & 31, wid = tid >> 5;
    const int r = lane >> 2, c2 = lane & 3;

    // one-time weight copy into smem
    {
        const uint4* s = (const uint4*)(&g_W1T[0][0][0]);
        uint4* d = (uint4*)(sm);
        for (int i = tid; i < 8448; i += 256) d[i] = s[i];
        const uint4* s2 = (const uint4*)(&g_W2T[0][0][0]);
        uint4* d2 = (uint4*)(sm + OFF_W2);
        for (int i = tid; i < 4160; i += 256) d2[i] = s2[i];
    }
    // cached biases
    float bv[4][2];
#pragma unroll
    for (int nt = 0; nt < 4; nt++) {
        int c = wid * 32 + nt * 8 + 2 * c2;
        bv[nt][0] = b1[c]; bv[nt][1] = b1[c + 1];
    }
    const int oc = wid * 8 + 2 * c2;
    const float b2v0 = b2[oc], b2v1 = b2[oc + 1];
    __syncthreads();

    float xr[16];
    int t = blockIdx.x;
    if (t < NTILES) {
#pragma unroll
        for (int j = 0; j < 16; j++) {
            int idx = tid + j * 256, rr = idx >> 7, c = idx & 127;
            size_t row = (size_t)t * TROWS + rr;
            xr[j] = (c < 64) ? A[row * 64 + c] : Bm[row * 64 + (c - 64)];
        }
    }

    for (; t < NTILES; t += gridDim.x) {
        // store current X tile (hi/lo split)
#pragma unroll
        for (int j = 0; j < 16; j++) {
            int idx = tid + j * 256, rr = idx >> 7, c = idx & 127;
            __nv_bfloat16 h = __float2bfloat16(xr[j]);
            sXhi[rr * W1S + c] = h;
            sXlo[rr * W1S + c] = __float2bfloat16(xr[j] - __bfloat162float(h));
        }
        __syncthreads();

        // prefetch next tile into registers
        int tn = t + gridDim.x;
        if (tn < NTILES) {
#pragma unroll
            for (int j = 0; j < 16; j++) {
                int idx = tid + j * 256, rr = idx >> 7, c = idx & 127;
                size_t row = (size_t)tn * TROWS + rr;
                xr[j] = (c < 64) ? A[row * 64 + c] : Bm[row * 64 + (c - 64)];
            }
        }

        // -------- stage 1: H = relu(X @ W1 + b1) --------
        float acc[2][4][4];
#pragma unroll
        for (int mt = 0; mt < 2; mt++)
#pragma unroll
            for (int nt = 0; nt < 4; nt++) {
                acc[mt][nt][0] = bv[nt][0]; acc[mt][nt][1] = bv[nt][1];
                acc[mt][nt][2] = bv[nt][0]; acc[mt][nt][3] = bv[nt][1];
            }
#pragma unroll
        for (int ks = 0; ks < 8; ks++) {
            const int k0 = ks * 16;
            unsigned ah[2][4], al[2][4];
#pragma unroll
            for (int mt = 0; mt < 2; mt++) {
                int row = mt * 16 + r;
                ah[mt][0] = *(const unsigned*)(sXhi + row * W1S + k0 + 2 * c2);
                ah[mt][1] = *(const unsigned*)(sXhi + (row + 8) * W1S + k0 + 2 * c2);
                ah[mt][2] = *(const unsigned*)(sXhi + row * W1S + k0 + 8 + 2 * c2);
                ah[mt][3] = *(const unsigned*)(sXhi + (row + 8) * W1S + k0 + 8 + 2 * c2);
                al[mt][0] = *(const unsigned*)(sXlo + row * W1S + k0 + 2 * c2);
                al[mt][1] = *(const unsigned*)(sXlo + (row + 8) * W1S + k0 + 2 * c2);
                al[mt][2] = *(const unsigned*)(sXlo + row * W1S + k0 + 8 + 2 * c2);
                al[mt][3] = *(const unsigned*)(sXlo + (row + 8) * W1S + k0 + 8 + 2 * c2);
            }
#pragma unroll
            for (int nt = 0; nt < 4; nt++) {
                int n = wid * 32 + nt * 8 + r;
                unsigned bh0 = *(const unsigned*)(sW1hi + n * W1S + k0 + 2 * c2);
                unsigned bh1 = *(const unsigned*)(sW1hi + n * W1S + k0 + 8 + 2 * c2);
                unsigned bl0 = *(const unsigned*)(sW1lo + n * W1S + k0 + 2 * c2);
                unsigned bl1 = *(const unsigned*)(sW1lo + n * W1S + k0 + 8 + 2 * c2);
#pragma unroll
                for (int mt = 0; mt < 2; mt++) {
                    mma16816(acc[mt][nt], ah[mt], bh0, bh1);
                    mma16816(acc[mt][nt], ah[mt], bl0, bl1);
                    mma16816(acc[mt][nt], al[mt], bh0, bh1);
                }
            }
        }
        __syncthreads();   // X consumed; buffer free for H

        float acc2[2][4];
#pragma unroll
        for (int mt = 0; mt < 2; mt++) {
            acc2[mt][0] = b2v0; acc2[mt][1] = b2v1;
            acc2[mt][2] = b2v0; acc2[mt][3] = b2v1;
        }

#pragma unroll
        for (int half = 0; half < 2; half++) {
            // store H panel: warps [4h, 4h+4) own cols [128h, 128h+128)
            if ((wid >> 2) == half) {
                const int cw = (wid & 3) * 32;
#pragma unroll
                for (int mt = 0; mt < 2; mt++)
#pragma unroll
                    for (int nt = 0; nt < 4; nt++) {
                        int row = mt * 16 + r;
                        int col = cw + nt * 8 + 2 * c2;
                        unsigned hp, lp;
                        splitpack(acc[mt][nt][0], acc[mt][nt][1], hp, lp);
                        *(unsigned*)(sXhi + row * W1S + col) = hp;
                        *(unsigned*)(sXlo + row * W1S + col) = lp;
                        splitpack(acc[mt][nt][2], acc[mt][nt][3], hp, lp);
                        *(unsigned*)(sXhi + (row + 8) * W1S + col) = hp;
                        *(unsigned*)(sXlo + (row + 8) * W1S + col) = lp;
                    }
            }
            __syncthreads();
            // stage-2 accumulate over this k-half
#pragma unroll
            for (int ks = 0; ks < 8; ks++) {
                const int k0 = ks * 16;
                unsigned ah[2][4], al[2][4];
#pragma unroll
                for (int mt = 0; mt < 2; mt++) {
                    int row = mt * 16 + r;
                    ah[mt][0] = *(const unsigned*)(sXhi + row * W1S + k0 + 2 * c2);
                    ah[mt][1] = *(const unsigned*)(sXhi + (row + 8) * W1S + k0 + 2 * c2);
                    ah[mt][2] = *(const unsigned*)(sXhi + row * W1S + k0 + 8 + 2 * c2);
                    ah[mt][3] = *(const unsigned*)(sXhi + (row + 8) * W1S + k0 + 8 + 2 * c2);
                    al[mt][0] = *(const unsigned*)(sXlo + row * W1S + k0 + 2 * c2);
                    al[mt][1] = *(const unsigned*)(sXlo + (row + 8) * W1S + k0 + 2 * c2);
                    al[mt][2] = *(const unsigned*)(sXlo + row * W1S + k0 + 8 + 2 * c2);
                    al[mt][3] = *(const unsigned*)(sXlo + (row + 8) * W1S + k0 + 8 + 2 * c2);
                }
                const int kg = half * 128 + k0;
                const int n = wid * 8 + r;
                unsigned bh0 = *(const unsigned*)(sW2hi + n * W2S + kg + 2 * c2);
                unsigned bh1 = *(const unsigned*)(sW2hi + n * W2S + kg + 8 + 2 * c2);
                unsigned bl0 = *(const unsigned*)(sW2lo + n * W2S + kg + 2 * c2);
                unsigned bl1 = *(const unsigned*)(sW2lo + n * W2S + kg + 8 + 2 * c2);
#pragma unroll
                for (int mt = 0; mt < 2; mt++) {
                    mma16816(acc2[mt], ah[mt], bh0, bh1);
                    mma16816(acc2[mt], ah[mt], bl0, bl1);
                    mma16816(acc2[mt], al[mt], bh0, bh1);
                }
            }
            __syncthreads();   // panel reads done before next overwrite
        }

        // -------- epilogue: mu = softplus(.) * gf --------
        const size_t row0 = (size_t)t * TROWS;
#pragma unroll
        for (int mt = 0; mt < 2; mt++) {
            int row = mt * 16 + r;
            float2 gf0 = *(const float2*)&g_gf[(row0 + row) * 64 + oc];
            float2 gf1 = *(const float2*)&g_gf[(row0 + row + 8) * 64 + oc];
            float2 o0, o1;
            o0.x = softplusf(acc2[mt][0]) * gf0.x;
            o0.y = softplusf(acc2[mt][1]) * gf0.y;
            o1.x = softplusf(acc2[mt][2]) * gf1.x;
            o1.y = softplusf(acc2[mt][3]) * gf1.y;
            *(float2*)&g_mu[(row0 + row) * 64 + oc] = o0;
            *(float2*)&g_mu[(row0 + row + 8) * 64 + oc] = o1;
        }
        __syncthreads();   // all H reads done before next tile's X store
    }
}

// ---------------------------------------------------------------------------
// Iteration kernel: register-resident stencil, 18 rows/thread, edge-only
// smem exchange. 128 interior L-rows per block, halo 8.
// ---------------------------------------------------------------------------
__global__ void __launch_bounds__(512) iter_kernel(
        const float* __restrict__ A, const float* __restrict__ Bm,
        float* __restrict__ hA, float* __restrict__ hB)
{
    __shared__ float sme[2][4][8][64];
    const int tid = threadIdx.x;
    const int c = tid & 63;
    const int j = tid >> 6;
    const int b = blockIdx.y;
    const int lbase = blockIdx.x * 128 - 8;
    const size_t base = ((size_t)b << 13);

    float D[18], S[18], MU[18];
#pragma unroll
    for (int rr = 0; rr < 18; rr++) {
        int l = (lbase + j * 18 + rr) & (LEN - 1);
        size_t g = (base + l) * 64 + c;
        float a = A[g], bb = Bm[g];
        D[rr] = a - bb;
        S[rr] = a + bb;
        MU[rr] = g_mu[g];
    }

#pragma unroll
    for (int k = 0; k < 6; k++) {
        const int p = k & 1;
        sme[p][0][j][c] = (1.f - 0.3f * MU[0])  * D[0];
        sme[p][1][j][c] = (1.f - 0.3f * MU[17]) * D[17];
        sme[p][2][j][c] = S[0];
        sme[p][3][j][c] = S[17];
        __syncthreads();
        float gylo = (j > 0) ? sme[p][1][j - 1][c] : 0.f;
        float gyhi = (j < 7) ? sme[p][0][j + 1][c] : 0.f;
        float gslo = (j > 0) ? sme[p][3][j - 1][c] : 0.f;
        float gshi = (j < 7) ? sme[p][2][j + 1][c] : 0.f;

        float yprev = gylo, sprev = gslo;
#pragma unroll
        for (int rr = 0; rr < 18; rr++) {
            float ycur  = (1.f - 0.3f * MU[rr]) * D[rr];
            float ynext = (rr < 17) ? (1.f - 0.3f * MU[rr + 1]) * D[rr + 1] : gyhi;
            float scur  = S[rr];
            float snext = (rr < 17) ? S[rr + 1] : gshi;
            D[rr] = 0.9f * ycur + 0.05f * (yprev + ynext);
            S[rr] = 0.9f * scur + 0.05f * (sprev + snext);
            yprev = ycur;
            sprev = scur;
        }
    }

    float esum = 0.f;
#pragma unroll
    for (int rr = 0; rr < 18; rr++) {
        int gidx = j * 18 + rr;
        if (gidx >= 8 && gidx < 136) {
            int l = blockIdx.x * 128 + (gidx - 8);
            size_t g = (base + l) * 64 + c;
            hA[g] = 0.5f * (S[rr] + D[rr]);
            hB[g] = 0.5f * (S[rr] - D[rr]);
            esum += 0.5f * MU[rr] * D[rr] * D[rr];
        }
    }

#pragma unroll
    for (int o = 16; o > 0; o >>= 1)
        esum += __shfl_xor_sync(0xffffffffu, esum, o);
    __shared__ float sred[16];
    if ((tid & 31) == 0) sred[tid >> 5] = esum;
    __syncthreads();
    if (tid == 0) {
        float tt = 0.f;
#pragma unroll
        for (int w = 0; w < 16; w++) tt += sred[w];
        g_epart[b * 64 + blockIdx.x] = tt;
    }
}

// ---------------------------------------------------------------------------
__global__ void __launch_bounds__(64) energy_reduce(float* __restrict__ energy)
{
    const int b = blockIdx.x;
    const int tid = threadIdx.x;
    float v = g_epart[b * 64 + tid];
#pragma unroll
    for (int o = 16; o > 0; o >>= 1)
        v += __shfl_xor_sync(0xffffffffu, v, o);
    __shared__ float s[2];
    if ((tid & 31) == 0) s[tid >> 5] = v;
    __syncthreads();
    if (tid == 0) energy[b] = s[0] + s[1];
}

// ---------------------------------------------------------------------------
extern "C" void kernel_launch(void* const* d_in, const int* in_sizes, int n_in,
                              void* d_out, int out_size)
{
    const float* A  = (const float*)d_in[0];
    const float* Bm = (const float*)d_in[1];
    const float* q  = (const float*)d_in[2];
    const float* W1 = (const float*)d_in[3];
    const float* b1 = (const float*)d_in[4];
    const float* W2 = (const float*)d_in[5];
    const float* b2 = (const float*)d_in[6];
    const float* Wq = (const float*)d_in[7];
    const float* bq = (const float*)d_in[8];

    float* out = (float*)d_out;
    float* hA = out;
    float* hB = out + (size_t)ROWS * DD;
    float* en = out + 2 * (size_t)ROWS * DD;

    prep_kernel<<<128, 256>>>(W1, W2);
    gate_kernel<<<ROWS / 64, 256>>>(q, Wq, bq);

    static int attr_set = 0;
    if (!attr_set) {
        cudaFuncSetAttribute(mu_kernel,
            cudaFuncAttributeMaxDynamicSharedMemorySize, SMEM_MU);
        attr_set = 1;
    }
    mu_kernel<<<MUGRID, 256, SMEM_MU>>>(A, Bm, b1, b2);

    iter_kernel<<<dim3(LEN / 128, BSZ), 512>>>(A, Bm, hA, hB);

    energy_reduce<<<BSZ, 64>>>(en);
}

// round 8
// speedup vs baseline: 5.6006x; 1.6863x over previous
#include <cuda_runtime.h>
#include <cuda_fp16.h>
#include <math.h>
#include <stdint.h>

#define BSZ 32
#define LEN 8192
#define ROWS (BSZ*LEN)
#define NTILES (ROWS/64)     // 4096 tiles of 64 rows
#define MUGRID 148

// fp16-element strides (all == 4 mod 32 words -> conflict-free)
#define S1 136
#define S2 264
#define SQ 72
// smem byte offsets
#define OW2 69632
#define OWQ 103424
#define OPH 112640
#define OPL 130048
#define OB1 147456
#define OB2 148480
#define OBQ 148736
#define SMEM_MU 148992

__device__ __align__(16) __half g_W1h[256 * 128];   // [n][k]
__device__ __align__(16) __half g_W2h[64 * 256];    // [n][k]
__device__ __align__(16) __half g_Wqh[64 * 64];     // [n][k]
__device__ float g_mu[(size_t)ROWS * 64];
__device__ float g_epart[BSZ * 64];

// ---------------------------------------------------------------------------
__global__ void __launch_bounds__(256) prep_kernel(
        const float* __restrict__ W1, const float* __restrict__ W2,
        const float* __restrict__ Wq)
{
    int i = blockIdx.x * blockDim.x + threadIdx.x;
    if (i < 256 * 128) {           // W1h[n][k] = fp16(W1[k][n])
        int n = i >> 7, k = i & 127;
        g_W1h[i] = __float2half_rn(W1[k * 256 + n]);
    }
    if (i < 64 * 256) {            // W2h[n][k] = fp16(W2[k][n])
        int n = i >> 8, k = i & 255;
        g_W2h[i] = __float2half_rn(W2[k * 64 + n]);
    }
    if (i < 64 * 64) {             // Wqh[n][k] = fp16(Wq[k][n])
        int n = i >> 6, k = i & 63;
        g_Wqh[i] = __float2half_rn(Wq[k * 64 + n]);
    }
}

// ---------------------------------------------------------------------------
__device__ __forceinline__ void mma16816h(float* c, const uint32_t* a,
                                          uint32_t b0, uint32_t b1)
{
    asm volatile(
        "mma.sync.aligned.m16n8k16.row.col.f32.f16.f16.f32 "
        "{%0,%1,%2,%3},{%4,%5,%6,%7},{%8,%9},{%0,%1,%2,%3};\n"
        : "+f"(c[0]), "+f"(c[1]), "+f"(c[2]), "+f"(c[3])
        : "r"(a[0]), "r"(a[1]), "r"(a[2]), "r"(a[3]), "r"(b0), "r"(b1));
}

__device__ __forceinline__ void ldsm4(uint32_t* d, uint32_t addr)
{
    asm volatile("ldmatrix.sync.aligned.m8n8.x4.shared.b16 {%0,%1,%2,%3}, [%4];"
        : "=r"(d[0]), "=r"(d[1]), "=r"(d[2]), "=r"(d[3]) : "r"(addr));
}

// split two fp32 into packed fp16 hi / lo pairs (x = hi + lo exactly-ish)
__device__ __forceinline__ void split2h(float x0, float x1, uint32_t& hp, uint32_t& lp)
{
    __half h0 = __float2half_rn(x0), h1 = __float2half_rn(x1);
    float l0 = x0 - __half2float(h0), l1 = x1 - __half2float(h1);
    hp = (uint32_t)__half_as_ushort(h0) | ((uint32_t)__half_as_ushort(h1) << 16);
    lp = (uint32_t)__half_as_ushort(__float2half_rn(l0)) |
         ((uint32_t)__half_as_ushort(__float2half_rn(l1)) << 16);
}

// ---------------------------------------------------------------------------
// Persistent mu kernel: 148 CTAs x 256 thr. Per 64-row tile:
//   H = relu([A;B] @ W1h + b1)   (x split 2-term fp16, W fp16)
//   M = H @ W2h + b2 ;  G = q @ Wqh + bq
//   mu = softplus(M) * (1 + 0.5*tanh(G))
// Weights resident in smem; H restaged through the X planes in 2 k-halves.
// ---------------------------------------------------------------------------
__global__ void __launch_bounds__(256, 1) mu_kernel(
        const float* __restrict__ A, const float* __restrict__ Bm,
        const float* __restrict__ qp,
        const float* __restrict__ b1, const float* __restrict__ b2,
        const float* __restrict__ bq)
{
    extern __shared__ char sm[];
    __half* sW1 = (__half*)sm;
    __half* sW2 = (__half*)(sm + OW2);
    __half* sWq = (__half*)(sm + OWQ);
    __half* pH  = (__half*)(sm + OPH);
    __half* pL  = (__half*)(sm + OPL);
    float* sB1 = (float*)(sm + OB1);
    float* sB2 = (float*)(sm + OB2);
    float* sBq = (float*)(sm + OBQ);

    const int tid = threadIdx.x, lane = tid & 31, wid = tid >> 5;
    const int r = lane >> 2, c2 = lane & 3;
    const uint32_t smb = (uint32_t)__cvta_generic_to_shared(sm);

    // one-time fills
    for (int i = tid; i < 256 * 128; i += 256) sW1[(i >> 7) * S1 + (i & 127)] = g_W1h[i];
    for (int i = tid; i < 64 * 256; i += 256)  sW2[(i >> 8) * S2 + (i & 255)] = g_W2h[i];
    for (int i = tid; i < 64 * 64; i += 256)   sWq[(i >> 6) * SQ + (i & 63)]  = g_Wqh[i];
    if (tid < 256) sB1[tid] = b1[tid];
    if (tid < 64) { sB2[tid] = b2[tid]; sBq[tid] = bq[tid]; }
    __syncthreads();

    // per-thread constants
    const int lrow = (lane & 7) + ((lane >> 3) & 1) * 8;   // ldmatrix row
    const int lk   = (lane >> 4) * 8;                      // ldmatrix k offset
    const uint32_t pHS = smb + OPH, pLS = smb + OPL;
    const int oc = (wid << 3) + (c2 << 1);
    const float b2v0 = sB2[oc], b2v1 = sB2[oc + 1];
    const float bqv0 = sBq[oc], bqv1 = sBq[oc + 1];
    float b1v[4][2];
#pragma unroll
    for (int nt = 0; nt < 4; nt++) {
        int n0 = (wid << 5) + (nt << 3) + (c2 << 1);
        b1v[nt][0] = sB1[n0]; b1v[nt][1] = sB1[n0 + 1];
    }

    for (int t = blockIdx.x; t < NTILES; t += gridDim.x) {
        const size_t row0 = (size_t)t * 64;

        // ---- X staging: 64 rows x 128 k (A | B), fp16 hi/lo planes ----
#pragma unroll
        for (int i = 0; i < 8; i++) {
            int e = i * 256 + tid;
            int row = e >> 5, kk = (e & 31) * 4;
            const float* src = (kk < 64) ? (A + (row0 + row) * 64 + kk)
                                         : (Bm + (row0 + row) * 64 + kk - 64);
            float4 v = *(const float4*)src;
            uint32_t h0, l0, h1, l1;
            split2h(v.x, v.y, h0, l0);
            split2h(v.z, v.w, h1, l1);
            *(uint2*)(pH + row * S1 + kk) = make_uint2(h0, h1);
            *(uint2*)(pL + row * S1 + kk) = make_uint2(l0, l1);
        }
        __syncthreads();

        // ---- stage 1: acc = X @ W1h (x 2-term) ----
        float acc[4][4][4];
#pragma unroll
        for (int mt = 0; mt < 4; mt++)
#pragma unroll
            for (int nt = 0; nt < 4; nt++)
#pragma unroll
                for (int i = 0; i < 4; i++) acc[mt][nt][i] = 0.f;
#pragma unroll
        for (int ks = 0; ks < 8; ks++) {
            const int k0 = ks * 16;
            uint32_t ah[4][4], al[4][4];
#pragma unroll
            for (int mt = 0; mt < 4; mt++) {
                uint32_t off = (uint32_t)(((16 * mt + lrow) * S1 + k0 + lk) * 2);
                ldsm4(ah[mt], pHS + off);
                ldsm4(al[mt], pLS + off);
            }
#pragma unroll
            for (int nt = 0; nt < 4; nt++) {
                int n = (wid << 5) + (nt << 3) + r;
                uint32_t b0 = *(const uint32_t*)(sW1 + n * S1 + k0 + (c2 << 1));
                uint32_t b1r = *(const uint32_t*)(sW1 + n * S1 + k0 + 8 + (c2 << 1));
#pragma unroll
                for (int mt = 0; mt < 4; mt++) {
                    mma16816h(acc[mt][nt], ah[mt], b0, b1r);
                    mma16816h(acc[mt][nt], al[mt], b0, b1r);
                }
            }
        }
        __syncthreads();

        // ---- stage 2 over two k-halves (H restaged through planes) ----
        float acc2[4][4];
#pragma unroll
        for (int mt = 0; mt < 4; mt++)
#pragma unroll
            for (int i = 0; i < 4; i++) acc2[mt][i] = 0.f;

#pragma unroll
        for (int half = 0; half < 2; half++) {
            if ((wid >> 2) == half) {
                const int cw = ((wid & 3) << 5);
#pragma unroll
                for (int mt = 0; mt < 4; mt++)
#pragma unroll
                    for (int nt = 0; nt < 4; nt++) {
                        int cl = cw + (nt << 3) + (c2 << 1);
                        uint32_t hp, lp;
                        float h0 = fmaxf(acc[mt][nt][0] + b1v[nt][0], 0.f);
                        float h1 = fmaxf(acc[mt][nt][1] + b1v[nt][1], 0.f);
                        split2h(h0, h1, hp, lp);
                        *(uint32_t*)(pH + (16 * mt + r) * S1 + cl) = hp;
                        *(uint32_t*)(pL + (16 * mt + r) * S1 + cl) = lp;
                        float h2 = fmaxf(acc[mt][nt][2] + b1v[nt][0], 0.f);
                        float h3 = fmaxf(acc[mt][nt][3] + b1v[nt][1], 0.f);
                        split2h(h2, h3, hp, lp);
                        *(uint32_t*)(pH + (16 * mt + 8 + r) * S1 + cl) = hp;
                        *(uint32_t*)(pL + (16 * mt + 8 + r) * S1 + cl) = lp;
                    }
            }
            __syncthreads();
#pragma unroll
            for (int ks = 0; ks < 8; ks++) {
                const int k0 = ks * 16;
                const int kg = half * 128 + k0;
                uint32_t ah[4][4], al[4][4];
#pragma unroll
                for (int mt = 0; mt < 4; mt++) {
                    uint32_t off = (uint32_t)(((16 * mt + lrow) * S1 + k0 + lk) * 2);
                    ldsm4(ah[mt], pHS + off);
                    ldsm4(al[mt], pLS + off);
                }
                int n = (wid << 3) + r;
                uint32_t b0 = *(const uint32_t*)(sW2 + n * S2 + kg + (c2 << 1));
                uint32_t b1r = *(const uint32_t*)(sW2 + n * S2 + kg + 8 + (c2 << 1));
#pragma unroll
                for (int mt = 0; mt < 4; mt++) {
                    mma16816h(acc2[mt], ah[mt], b0, b1r);
                    mma16816h(acc2[mt], al[mt], b0, b1r);
                }
            }
            __syncthreads();
        }

        // ---- gate: q @ Wqh ----
#pragma unroll
        for (int i = 0; i < 4; i++) {
            int e = i * 256 + tid;
            int row = e >> 4, kk = (e & 15) * 4;
            float4 v = *(const float4*)(qp + (row0 + row) * 64 + kk);
            uint32_t h0, l0, h1, l1;
            split2h(v.x, v.y, h0, l0);
            split2h(v.z, v.w, h1, l1);
            *(uint2*)(pH + row * S1 + kk) = make_uint2(h0, h1);
            *(uint2*)(pL + row * S1 + kk) = make_uint2(l0, l1);
        }
        __syncthreads();

        float accg[4][4];
#pragma unroll
        for (int mt = 0; mt < 4; mt++)
#pragma unroll
            for (int i = 0; i < 4; i++) accg[mt][i] = 0.f;
#pragma unroll
        for (int ks = 0; ks < 4; ks++) {
            const int k0 = ks * 16;
            uint32_t ah[4][4], al[4][4];
#pragma unroll
            for (int mt = 0; mt < 4; mt++) {
                uint32_t off = (uint32_t)(((16 * mt + lrow) * S1 + k0 + lk) * 2);
                ldsm4(ah[mt], pHS + off);
                ldsm4(al[mt], pLS + off);
            }
            int n = (wid << 3) + r;
            uint32_t b0 = *(const uint32_t*)(sWq + n * SQ + k0 + (c2 << 1));
            uint32_t b1r = *(const uint32_t*)(sWq + n * SQ + k0 + 8 + (c2 << 1));
#pragma unroll
            for (int mt = 0; mt < 4; mt++) {
                mma16816h(accg[mt], ah[mt], b0, b1r);
                mma16816h(accg[mt], al[mt], b0, b1r);
            }
        }

        // ---- epilogue ----
#pragma unroll
        for (int mt = 0; mt < 4; mt++) {
            int row = 16 * mt + r;
            float m0 = acc2[mt][0] + b2v0, m1 = acc2[mt][1] + b2v1;
            float sp0 = fmaxf(m0, 0.f) + log1pf(expf(-fabsf(m0)));
            float sp1 = fmaxf(m1, 0.f) + log1pf(expf(-fabsf(m1)));
            float g0 = tanhf(accg[mt][0] + bqv0), g1 = tanhf(accg[mt][1] + bqv1);
            *(float2*)&g_mu[(row0 + row) * 64 + oc] =
                make_float2(sp0 * (1.f + 0.5f * g0), sp1 * (1.f + 0.5f * g1));
            float m2 = acc2[mt][2] + b2v0, m3 = acc2[mt][3] + b2v1;
            float sp2 = fmaxf(m2, 0.f) + log1pf(expf(-fabsf(m2)));
            float sp3 = fmaxf(m3, 0.f) + log1pf(expf(-fabsf(m3)));
            float g2 = tanhf(accg[mt][2] + bqv0), g3 = tanhf(accg[mt][3] + bqv1);
            *(float2*)&g_mu[(row0 + row + 8) * 64 + oc] =
                make_float2(sp2 * (1.f + 0.5f * g2), sp3 * (1.f + 0.5f * g3));
        }
        __syncthreads();
    }
}

// ---------------------------------------------------------------------------
// Iteration kernel: register-resident stencil, 18 rows/thread, edge-only
// smem exchange. 128 interior L-rows per block, halo 8.
// ---------------------------------------------------------------------------
__global__ void __launch_bounds__(512) iter_kernel(
        const float* __restrict__ A, const float* __restrict__ Bm,
        float* __restrict__ hA, float* __restrict__ hB)
{
    __shared__ float sme[2][4][8][64];
    const int tid = threadIdx.x;
    const int c = tid & 63;
    const int j = tid >> 6;
    const int b = blockIdx.y;
    const int lbase = blockIdx.x * 128 - 8;
    const size_t base = ((size_t)b << 13);

    float D[18], S[18], MU[18];
#pragma unroll
    for (int rr = 0; rr < 18; rr++) {
        int l = (lbase + j * 18 + rr) & (LEN - 1);
        size_t g = (base + l) * 64 + c;
        float a = A[g], bb = Bm[g];
        D[rr] = a - bb;
        S[rr] = a + bb;
        MU[rr] = g_mu[g];
    }

#pragma unroll
    for (int k = 0; k < 6; k++) {
        const int p = k & 1;
        sme[p][0][j][c] = (1.f - 0.3f * MU[0])  * D[0];
        sme[p][1][j][c] = (1.f - 0.3f * MU[17]) * D[17];
        sme[p][2][j][c] = S[0];
        sme[p][3][j][c] = S[17];
        __syncthreads();
        float gylo = (j > 0) ? sme[p][1][j - 1][c] : 0.f;
        float gyhi = (j < 7) ? sme[p][0][j + 1][c] : 0.f;
        float gslo = (j > 0) ? sme[p][3][j - 1][c] : 0.f;
        float gshi = (j < 7) ? sme[p][2][j + 1][c] : 0.f;

        float yprev = gylo, sprev = gslo;
#pragma unroll
        for (int rr = 0; rr < 18; rr++) {
            float ycur  = (1.f - 0.3f * MU[rr]) * D[rr];
            float ynext = (rr < 17) ? (1.f - 0.3f * MU[rr + 1]) * D[rr + 1] : gyhi;
            float scur  = S[rr];
            float snext = (rr < 17) ? S[rr + 1] : gshi;
            D[rr] = 0.9f * ycur + 0.05f * (yprev + ynext);
            S[rr] = 0.9f * scur + 0.05f * (sprev + snext);
            yprev = ycur;
            sprev = scur;
        }
    }

    float esum = 0.f;
#pragma unroll
    for (int rr = 0; rr < 18; rr++) {
        int gidx = j * 18 + rr;
        if (gidx >= 8 && gidx < 136) {
            int l = blockIdx.x * 128 + (gidx - 8);
            size_t g = (base + l) * 64 + c;
            hA[g] = 0.5f * (S[rr] + D[rr]);
            hB[g] = 0.5f * (S[rr] - D[rr]);
            esum += 0.5f * MU[rr] * D[rr] * D[rr];
        }
    }

#pragma unroll
    for (int o = 16; o > 0; o >>= 1)
        esum += __shfl_xor_sync(0xffffffffu, esum, o);
    __shared__ float sred[16];
    if ((tid & 31) == 0) sred[tid >> 5] = esum;
    __syncthreads();
    if (tid == 0) {
        float tt = 0.f;
#pragma unroll
        for (int w = 0; w < 16; w++) tt += sred[w];
        g_epart[b * 64 + blockIdx.x] = tt;
    }
}

// ---------------------------------------------------------------------------
__global__ void __launch_bounds__(64) energy_reduce(float* __restrict__ energy)
{
    const int b = blockIdx.x;
    const int tid = threadIdx.x;
    float v = g_epart[b * 64 + tid];
#pragma unroll
    for (int o = 16; o > 0; o >>= 1)
        v += __shfl_xor_sync(0xffffffffu, v, o);
    __shared__ float s[2];
    if ((tid & 31) == 0) s[tid >> 5] = v;
    __syncthreads();
    if (tid == 0) energy[b] = s[0] + s[1];
}

// ---------------------------------------------------------------------------
extern "C" void kernel_launch(void* const* d_in, const int* in_sizes, int n_in,
                              void* d_out, int out_size)
{
    const float* A  = (const float*)d_in[0];
    const float* Bm = (const float*)d_in[1];
    const float* q  = (const float*)d_in[2];
    const float* W1 = (const float*)d_in[3];
    const float* b1 = (const float*)d_in[4];
    const float* W2 = (const float*)d_in[5];
    const float* b2 = (const float*)d_in[6];
    const float* Wq = (const float*)d_in[7];
    const float* bq = (const float*)d_in[8];

    float* out = (float*)d_out;
    float* hA = out;
    float* hB = out + (size_t)ROWS * 64;
    float* en = out + 2 * (size_t)ROWS * 64;

    prep_kernel<<<128, 256>>>(W1, W2, Wq);

    static int attr_set = 0;
    if (!attr_set) {
        cudaFuncSetAttribute(mu_kernel,
            cudaFuncAttributeMaxDynamicSharedMemorySize, SMEM_MU);
        attr_set = 1;
    }
    mu_kernel<<<MUGRID, 256, SMEM_MU>>>(A, Bm, q, b1, b2, bq);

    iter_kernel<<<dim3(LEN / 128, BSZ), 512>>>(A, Bm, hA, hB);

    energy_reduce<<<BSZ, 64>>>(en);
}

// round 10
// speedup vs baseline: 6.1893x; 1.1051x over previous
#include <cuda_runtime.h>
#include <cuda_fp16.h>
#include <math.h>
#include <stdint.h>

#define BSZ 32
#define LEN 8192
#define ROWS (BSZ*LEN)
#define NTILES (ROWS/64)     // 4096 tiles of 64 rows
#define MUGRID 148

// fp16-element strides (all == 4 mod 32 words -> conflict-free)
#define S1 136
#define S2 264
#define SQ 72
// smem byte offsets
#define OW2 69632
#define OWQ 103424
#define OPXH 112640
#define OPXL 130048
#define OPHH 147456
#define OPHL 181248
#define OB1 215040
#define OB2 216064
#define OBQ 216320
#define SMEM_MU 216576

__device__ __align__(16) __half g_W1h[256 * 128];   // [n][k]
__device__ __align__(16) __half g_W2h[64 * 256];    // [n][k]
__device__ __align__(16) __half g_Wqh[64 * 64];     // [n][k]
__device__ float g_mu[(size_t)ROWS * 64];
__device__ float g_epart[BSZ * 128];

// ---------------------------------------------------------------------------
__global__ void __launch_bounds__(256) prep_kernel(
        const float* __restrict__ W1, const float* __restrict__ W2,
        const float* __restrict__ Wq)
{
    int i = blockIdx.x * blockDim.x + threadIdx.x;
    if (i < 256 * 128) {           // W1h[n][k] = fp16(W1[k][n])
        int n = i >> 7, k = i & 127;
        g_W1h[i] = __float2half_rn(W1[k * 256 + n]);
    }
    if (i < 64 * 256) {            // W2h[n][k] = fp16(W2[k][n])
        int n = i >> 8, k = i & 255;
        g_W2h[i] = __float2half_rn(W2[k * 64 + n]);
    }
    if (i < 64 * 64) {             // Wqh[n][k] = fp16(Wq[k][n])
        int n = i >> 6, k = i & 63;
        g_Wqh[i] = __float2half_rn(Wq[k * 64 + n]);
    }
}

// ---------------------------------------------------------------------------
__device__ __forceinline__ void mma16816h(float* c, const uint32_t* a,
                                          uint32_t b0, uint32_t b1)
{
    asm volatile(
        "mma.sync.aligned.m16n8k16.row.col.f32.f16.f16.f32 "
        "{%0,%1,%2,%3},{%4,%5,%6,%7},{%8,%9},{%0,%1,%2,%3};\n"
        : "+f"(c[0]), "+f"(c[1]), "+f"(c[2]), "+f"(c[3])
        : "r"(a[0]), "r"(a[1]), "r"(a[2]), "r"(a[3]), "r"(b0), "r"(b1));
}

__device__ __forceinline__ void ldsm4(uint32_t* d, uint32_t addr)
{
    asm volatile("ldmatrix.sync.aligned.m8n8.x4.shared.b16 {%0,%1,%2,%3}, [%4];"
        : "=r"(d[0]), "=r"(d[1]), "=r"(d[2]), "=r"(d[3]) : "r"(addr));
}

// split two fp32 into packed fp16 hi / lo pairs
__device__ __forceinline__ void split2h(float x0, float x1, uint32_t& hp, uint32_t& lp)
{
    __half h0 = __float2half_rn(x0), h1 = __float2half_rn(x1);
    float l0 = x0 - __half2float(h0), l1 = x1 - __half2float(h1);
    hp = (uint32_t)__half_as_ushort(h0) | ((uint32_t)__half_as_ushort(h1) << 16);
    lp = (uint32_t)__half_as_ushort(__float2half_rn(l0)) |
         ((uint32_t)__half_as_ushort(__float2half_rn(l1)) << 16);
}

// ---------------------------------------------------------------------------
// Persistent mu kernel: 148 CTAs x 256 thr, 64-row tiles, fp16 2-term split.
// Pipeline per tile: store X -> (prefetch q) stage1 -> store H+q
// -> (prefetch next X) stage2 + gate -> epilogue. 4 syncs/tile.
// ---------------------------------------------------------------------------
__global__ void __launch_bounds__(256, 1) mu_kernel(
        const float* __restrict__ A, const float* __restrict__ Bm,
        const float* __restrict__ qp,
        const float* __restrict__ b1, const float* __restrict__ b2,
        const float* __restrict__ bq)
{
    extern __shared__ char sm[];
    __half* sW1 = (__half*)sm;
    __half* sW2 = (__half*)(sm + OW2);
    __half* sWq = (__half*)(sm + OWQ);
    __half* pXH = (__half*)(sm + OPXH);
    __half* pXL = (__half*)(sm + OPXL);
    __half* pHH = (__half*)(sm + OPHH);
    __half* pHL = (__half*)(sm + OPHL);
    float* sB1 = (float*)(sm + OB1);
    float* sB2 = (float*)(sm + OB2);
    float* sBq = (float*)(sm + OBQ);

    const int tid = threadIdx.x, lane = tid & 31, wid = tid >> 5;
    const int r = lane >> 2, c2 = lane & 3;
    const uint32_t smb = (uint32_t)__cvta_generic_to_shared(sm);

    // one-time fills
    for (int i = tid; i < 256 * 128; i += 256) sW1[(i >> 7) * S1 + (i & 127)] = g_W1h[i];
    for (int i = tid; i < 64 * 256; i += 256)  sW2[(i >> 8) * S2 + (i & 255)] = g_W2h[i];
    for (int i = tid; i < 64 * 64; i += 256)   sWq[(i >> 6) * SQ + (i & 63)]  = g_Wqh[i];
    if (tid < 256) sB1[tid] = b1[tid];
    if (tid < 64) { sB2[tid] = b2[tid]; sBq[tid] = bq[tid]; }
    __syncthreads();

    const int lrow = (lane & 7) + ((lane >> 3) & 1) * 8;   // ldmatrix row
    const int lk   = (lane >> 4) * 8;                      // ldmatrix k offset
    const uint32_t pXHs = smb + OPXH, pXLs = smb + OPXL;
    const uint32_t pHHs = smb + OPHH, pHLs = smb + OPHL;
    const int oc = (wid << 3) + (c2 << 1);
    const float b2v0 = sB2[oc], b2v1 = sB2[oc + 1];
    const float bqv0 = sBq[oc], bqv1 = sBq[oc + 1];
    float b1v[4][2];
#pragma unroll
    for (int nt = 0; nt < 4; nt++) {
        int n0 = (wid << 5) + (nt << 3) + (c2 << 1);
        b1v[nt][0] = sB1[n0]; b1v[nt][1] = sB1[n0 + 1];
    }

    // prologue: load first tile's X into regs
    float xr[32];
    {
        int t0 = blockIdx.x;
        if (t0 < NTILES) {
            const size_t row0 = (size_t)t0 * 64;
#pragma unroll
            for (int i = 0; i < 8; i++) {
                int e = i * 256 + tid;
                int row = e >> 5, kk = (e & 31) * 4;
                const float* src = (kk < 64) ? (A + (row0 + row) * 64 + kk)
                                             : (Bm + (row0 + row) * 64 + kk - 64);
                float4 v = *(const float4*)src;
                xr[4 * i] = v.x; xr[4 * i + 1] = v.y;
                xr[4 * i + 2] = v.z; xr[4 * i + 3] = v.w;
            }
        }
    }

    for (int t = blockIdx.x; t < NTILES; t += gridDim.x) {
        const size_t row0 = (size_t)t * 64;

        // ---- store X planes from prefetched regs ----
#pragma unroll
        for (int i = 0; i < 8; i++) {
            int e = i * 256 + tid;
            int row = e >> 5, kk = (e & 31) * 4;
            uint32_t h0, l0, h1, l1;
            split2h(xr[4 * i], xr[4 * i + 1], h0, l0);
            split2h(xr[4 * i + 2], xr[4 * i + 3], h1, l1);
            *(uint2*)(pXH + row * S1 + kk) = make_uint2(h0, h1);
            *(uint2*)(pXL + row * S1 + kk) = make_uint2(l0, l1);
        }
        __syncthreads();                                  // (a)

        // prefetch q for this tile (consumed after stage1)
        float qr[16];
#pragma unroll
        for (int i = 0; i < 4; i++) {
            int e = i * 256 + tid;
            int row = e >> 4, kk = (e & 15) * 4;
            float4 v = *(const float4*)(qp + (row0 + row) * 64 + kk);
            qr[4 * i] = v.x; qr[4 * i + 1] = v.y;
            qr[4 * i + 2] = v.z; qr[4 * i + 3] = v.w;
        }

        // ---- stage 1: acc = X @ W1h ----
        float acc[4][4][4];
#pragma unroll
        for (int mt = 0; mt < 4; mt++)
#pragma unroll
            for (int nt = 0; nt < 4; nt++)
#pragma unroll
                for (int i = 0; i < 4; i++) acc[mt][nt][i] = 0.f;
#pragma unroll
        for (int ks = 0; ks < 8; ks++) {
            const int k0 = ks * 16;
            uint32_t ah[4][4], al[4][4];
#pragma unroll
            for (int mt = 0; mt < 4; mt++) {
                uint32_t off = (uint32_t)(((16 * mt + lrow) * S1 + k0 + lk) * 2);
                ldsm4(ah[mt], pXHs + off);
                ldsm4(al[mt], pXLs + off);
            }
#pragma unroll
            for (int nt = 0; nt < 4; nt++) {
                int n = (wid << 5) + (nt << 3) + r;
                uint32_t wb0 = *(const uint32_t*)(sW1 + n * S1 + k0 + (c2 << 1));
                uint32_t wb1 = *(const uint32_t*)(sW1 + n * S1 + k0 + 8 + (c2 << 1));
#pragma unroll
                for (int mt = 0; mt < 4; mt++) {
                    mma16816h(acc[mt][nt], ah[mt], wb0, wb1);
                    mma16816h(acc[mt][nt], al[mt], wb0, wb1);
                }
            }
        }
        __syncthreads();                                  // (b)

        // ---- store H (all warps, full width) + q into dead X planes ----
#pragma unroll
        for (int mt = 0; mt < 4; mt++)
#pragma unroll
            for (int nt = 0; nt < 4; nt++) {
                int cl = (wid << 5) + (nt << 3) + (c2 << 1);
                uint32_t hp, lp;
                float h0 = fmaxf(acc[mt][nt][0] + b1v[nt][0], 0.f);
                float h1 = fmaxf(acc[mt][nt][1] + b1v[nt][1], 0.f);
                split2h(h0, h1, hp, lp);
                *(uint32_t*)(pHH + (16 * mt + r) * S2 + cl) = hp;
                *(uint32_t*)(pHL + (16 * mt + r) * S2 + cl) = lp;
                float h2 = fmaxf(acc[mt][nt][2] + b1v[nt][0], 0.f);
                float h3 = fmaxf(acc[mt][nt][3] + b1v[nt][1], 0.f);
                split2h(h2, h3, hp, lp);
                *(uint32_t*)(pHH + (16 * mt + 8 + r) * S2 + cl) = hp;
                *(uint32_t*)(pHL + (16 * mt + 8 + r) * S2 + cl) = lp;
            }
#pragma unroll
        for (int i = 0; i < 4; i++) {
            int e = i * 256 + tid;
            int row = e >> 4, kk = (e & 15) * 4;
            uint32_t h0, l0, h1, l1;
            split2h(qr[4 * i], qr[4 * i + 1], h0, l0);
            split2h(qr[4 * i + 2], qr[4 * i + 3], h1, l1);
            *(uint2*)(pXH + row * S1 + kk) = make_uint2(h0, h1);
            *(uint2*)(pXL + row * S1 + kk) = make_uint2(l0, l1);
        }

        // prefetch next tile's X (overlaps stage2/gate MMAs)
        {
            int tn = t + gridDim.x;
            if (tn < NTILES) {
                const size_t rown = (size_t)tn * 64;
#pragma unroll
                for (int i = 0; i < 8; i++) {
                    int e = i * 256 + tid;
                    int row = e >> 5, kk = (e & 31) * 4;
                    const float* src = (kk < 64) ? (A + (rown + row) * 64 + kk)
                                                 : (Bm + (rown + row) * 64 + kk - 64);
                    float4 v = *(const float4*)src;
                    xr[4 * i] = v.x; xr[4 * i + 1] = v.y;
                    xr[4 * i + 2] = v.z; xr[4 * i + 3] = v.w;
                }
            }
        }
        __syncthreads();                                  // (c)

        // ---- stage 2: M = H @ W2h (K=256, single pass) ----
        float acc2[4][4];
#pragma unroll
        for (int mt = 0; mt < 4; mt++)
#pragma unroll
            for (int i = 0; i < 4; i++) acc2[mt][i] = 0.f;
#pragma unroll
        for (int ks = 0; ks < 16; ks++) {
            const int k0 = ks * 16;
            uint32_t ah[4][4], al[4][4];
#pragma unroll
            for (int mt = 0; mt < 4; mt++) {
                uint32_t off = (uint32_t)(((16 * mt + lrow) * S2 + k0 + lk) * 2);
                ldsm4(ah[mt], pHHs + off);
                ldsm4(al[mt], pHLs + off);
            }
            int n = (wid << 3) + r;
            uint32_t wb0 = *(const uint32_t*)(sW2 + n * S2 + k0 + (c2 << 1));
            uint32_t wb1 = *(const uint32_t*)(sW2 + n * S2 + k0 + 8 + (c2 << 1));
#pragma unroll
            for (int mt = 0; mt < 4; mt++) {
                mma16816h(acc2[mt], ah[mt], wb0, wb1);
                mma16816h(acc2[mt], al[mt], wb0, wb1);
            }
        }

        // ---- gate: G = q @ Wqh ----
        float accg[4][4];
#pragma unroll
        for (int mt = 0; mt < 4; mt++)
#pragma unroll
            for (int i = 0; i < 4; i++) accg[mt][i] = 0.f;
#pragma unroll
        for (int ks = 0; ks < 4; ks++) {
            const int k0 = ks * 16;
            uint32_t ah[4][4], al[4][4];
#pragma unroll
            for (int mt = 0; mt < 4; mt++) {
                uint32_t off = (uint32_t)(((16 * mt + lrow) * S1 + k0 + lk) * 2);
                ldsm4(ah[mt], pXHs + off);
                ldsm4(al[mt], pXLs + off);
            }
            int n = (wid << 3) + r;
            uint32_t wb0 = *(const uint32_t*)(sWq + n * SQ + k0 + (c2 << 1));
            uint32_t wb1 = *(const uint32_t*)(sWq + n * SQ + k0 + 8 + (c2 << 1));
#pragma unroll
            for (int mt = 0; mt < 4; mt++) {
                mma16816h(accg[mt], ah[mt], wb0, wb1);
                mma16816h(accg[mt], al[mt], wb0, wb1);
            }
        }

        // ---- epilogue ----
#pragma unroll
        for (int mt = 0; mt < 4; mt++) {
            int row = 16 * mt + r;
            float m0 = acc2[mt][0] + b2v0, m1 = acc2[mt][1] + b2v1;
            float sp0 = fmaxf(m0, 0.f) + log1pf(expf(-fabsf(m0)));
            float sp1 = fmaxf(m1, 0.f) + log1pf(expf(-fabsf(m1)));
            float g0 = tanhf(accg[mt][0] + bqv0), g1 = tanhf(accg[mt][1] + bqv1);
            *(float2*)&g_mu[(row0 + row) * 64 + oc] =
                make_float2(sp0 * (1.f + 0.5f * g0), sp1 * (1.f + 0.5f * g1));
            float m2 = acc2[mt][2] + b2v0, m3 = acc2[mt][3] + b2v1;
            float sp2 = fmaxf(m2, 0.f) + log1pf(expf(-fabsf(m2)));
            float sp3 = fmaxf(m3, 0.f) + log1pf(expf(-fabsf(m3)));
            float g2 = tanhf(accg[mt][2] + bqv0), g3 = tanhf(accg[mt][3] + bqv1);
            *(float2*)&g_mu[(row0 + row + 8) * 64 + oc] =
                make_float2(sp2 * (1.f + 0.5f * g2), sp3 * (1.f + 0.5f * g3));
        }
        __syncthreads();                                  // (d)
    }
}

// ---------------------------------------------------------------------------
// Iteration kernel: 10 rows/thread, TL=64 interior, halo 8, 2 blocks/SM.
// ---------------------------------------------------------------------------
__global__ void __launch_bounds__(512, 2) iter_kernel(
        const float* __restrict__ A, const float* __restrict__ Bm,
        float* __restrict__ hA, float* __restrict__ hB)
{
    __shared__ float sme[2][4][8][64];
    const int tid = threadIdx.x;
    const int c = tid & 63;
    const int j = tid >> 6;
    const int b = blockIdx.y;
    const int lbase = blockIdx.x * 64 - 8;
    const size_t base = ((size_t)b << 13);

    float D[10], S[10], MU[10];
#pragma unroll
    for (int rr = 0; rr < 10; rr++) {
        int l = (lbase + j * 10 + rr) & (LEN - 1);
        size_t g = (base + l) * 64 + c;
        float a = A[g], bb = Bm[g];
        D[rr] = a - bb;
        S[rr] = a + bb;
        MU[rr] = g_mu[g];
    }

#pragma unroll
    for (int k = 0; k < 6; k++) {
        const int p = k & 1;
        sme[p][0][j][c] = (1.f - 0.3f * MU[0]) * D[0];
        sme[p][1][j][c] = (1.f - 0.3f * MU[9]) * D[9];
        sme[p][2][j][c] = S[0];
        sme[p][3][j][c] = S[9];
        __syncthreads();
        float gylo = (j > 0) ? sme[p][1][j - 1][c] : 0.f;
        float gyhi = (j < 7) ? sme[p][0][j + 1][c] : 0.f;
        float gslo = (j > 0) ? sme[p][3][j - 1][c] : 0.f;
        float gshi = (j < 7) ? sme[p][2][j + 1][c] : 0.f;

        float yprev = gylo, sprev = gslo;
#pragma unroll
        for (int rr = 0; rr < 10; rr++) {
            float ycur  = (1.f - 0.3f * MU[rr]) * D[rr];
            float ynext = (rr < 9) ? (1.f - 0.3f * MU[rr + 1]) * D[rr + 1] : gyhi;
            float scur  = S[rr];
            float snext = (rr < 9) ? S[rr + 1] : gshi;
            D[rr] = 0.9f * ycur + 0.05f * (yprev + ynext);
            S[rr] = 0.9f * scur + 0.05f * (sprev + snext);
            yprev = ycur;
            sprev = scur;
        }
    }

    float esum = 0.f;
#pragma unroll
    for (int rr = 0; rr < 10; rr++) {
        int gidx = j * 10 + rr;
        if (gidx >= 8 && gidx < 72) {
            int l = blockIdx.x * 64 + (gidx - 8);
            size_t g = (base + l) * 64 + c;
            hA[g] = 0.5f * (S[rr] + D[rr]);
            hB[g] = 0.5f * (S[rr] - D[rr]);
            esum += 0.5f * MU[rr] * D[rr] * D[rr];
        }
    }

#pragma unroll
    for (int o = 16; o > 0; o >>= 1)
        esum += __shfl_xor_sync(0xffffffffu, esum, o);
    __shared__ float sred[16];
    if ((tid & 31) == 0) sred[tid >> 5] = esum;
    __syncthreads();
    if (tid == 0) {
        float tt = 0.f;
#pragma unroll
        for (int w = 0; w < 16; w++) tt += sred[w];
        g_epart[b * 128 + blockIdx.x] = tt;
    }
}

// ---------------------------------------------------------------------------
__global__ void __launch_bounds__(128) energy_reduce(float* __restrict__ energy)
{
    const int b = blockIdx.x;
    const int tid = threadIdx.x;
    float v = g_epart[b * 128 + tid];
#pragma unroll
    for (int o = 16; o > 0; o >>= 1)
        v += __shfl_xor_sync(0xffffffffu, v, o);
    __shared__ float s[4];
    if ((tid & 31) == 0) s[tid >> 5] = v;
    __syncthreads();
    if (tid == 0) energy[b] = s[0] + s[1] + s[2] + s[3];
}

// ---------------------------------------------------------------------------
extern "C" void kernel_launch(void* const* d_in, const int* in_sizes, int n_in,
                              void* d_out, int out_size)
{
    const float* A  = (const float*)d_in[0];
    const float* Bm = (const float*)d_in[1];
    const float* q  = (const float*)d_in[2];
    const float* W1 = (const float*)d_in[3];
    const float* b1 = (const float*)d_in[4];
    const float* W2 = (const float*)d_in[5];
    const float* b2 = (const float*)d_in[6];
    const float* Wq = (const float*)d_in[7];
    const float* bq = (const float*)d_in[8];

    float* out = (float*)d_out;
    float* hA = out;
    float* hB = out + (size_t)ROWS * 64;
    float* en = out + 2 * (size_t)ROWS * 64;

    prep_kernel<<<128, 256>>>(W1, W2, Wq);

    static int attr_set = 0;
    if (!attr_set) {
        cudaFuncSetAttribute(mu_kernel,
            cudaFuncAttributeMaxDynamicSharedMemorySize, SMEM_MU);
        attr_set = 1;
    }
    mu_kernel<<<MUGRID, 256, SMEM_MU>>>(A, Bm, q, b1, b2, bq);

    iter_kernel<<<dim3(LEN / 64, BSZ), 512>>>(A, Bm, hA, hB);

    energy_reduce<<<BSZ, 128>>>(en);
}

// round 11
// speedup vs baseline: 8.4628x; 1.3673x over previous
#include <cuda_runtime.h>
#include <cuda_fp16.h>
#include <math.h>
#include <stdint.h>

#define BSZ 32
#define LEN 8192
#define ROWS (BSZ*LEN)
#define NTILES (ROWS/64)     // 4096 tiles of 64 rows
#define MUGRID 148

// fp16-element strides (all == 4 mod 32 words -> conflict-free)
#define S1 136
#define S2 264
#define SQ 72
// smem byte offsets
#define OW2  69632
#define OWQ  103424
#define OPX  112640
#define OPH  130048
#define OB1  163840
#define OB2  164864
#define OBQ  165120
#define SMEM_MU 165376

__device__ float g_mu[(size_t)ROWS * 64];
__device__ float g_epart[BSZ * 128];

// ---------------------------------------------------------------------------
__device__ __forceinline__ void mma16816h(float* c, const uint32_t* a,
                                          uint32_t b0, uint32_t b1)
{
    asm volatile(
        "mma.sync.aligned.m16n8k16.row.col.f32.f16.f16.f32 "
        "{%0,%1,%2,%3},{%4,%5,%6,%7},{%8,%9},{%0,%1,%2,%3};\n"
        : "+f"(c[0]), "+f"(c[1]), "+f"(c[2]), "+f"(c[3])
        : "r"(a[0]), "r"(a[1]), "r"(a[2]), "r"(a[3]), "r"(b0), "r"(b1));
}

__device__ __forceinline__ void ldsm4(uint32_t* d, uint32_t addr)
{
    asm volatile("ldmatrix.sync.aligned.m8n8.x4.shared.b16 {%0,%1,%2,%3}, [%4];"
        : "=r"(d[0]), "=r"(d[1]), "=r"(d[2]), "=r"(d[3]) : "r"(addr));
}

__device__ __forceinline__ uint32_t pack2h(float x0, float x1)
{
    __half2 h = __floats2half2_rn(x0, x1);
    return *(uint32_t*)&h;
}

// ---------------------------------------------------------------------------
// Persistent mu kernel: 148 CTAs x 256 thr, 64-row tiles, plain fp16 MMA.
//   H = relu([A;B] @ W1h + b1); M = H @ W2h + b2; G = q @ Wqh + bq
//   mu = softplus(M) * (1 + 0.5*tanh(G))
// Weights converted fp32->fp16 once per CTA into resident smem.
// Pipeline per tile: store X -> (prefetch q) stage1 -> store H+q
// -> (prefetch next X) stage2 + gate -> epilogue. 4 syncs/tile.
// ---------------------------------------------------------------------------
__global__ void __launch_bounds__(256, 1) mu_kernel(
        const float* __restrict__ A, const float* __restrict__ Bm,
        const float* __restrict__ qp,
        const float* __restrict__ W1, const float* __restrict__ b1,
        const float* __restrict__ W2, const float* __restrict__ b2,
        const float* __restrict__ Wq, const float* __restrict__ bq)
{
    extern __shared__ char sm[];
    __half* sW1 = (__half*)sm;
    __half* sW2 = (__half*)(sm + OW2);
    __half* sWq = (__half*)(sm + OWQ);
    __half* pX  = (__half*)(sm + OPX);
    __half* pH  = (__half*)(sm + OPH);
    float* sB1 = (float*)(sm + OB1);
    float* sB2 = (float*)(sm + OB2);
    float* sBq = (float*)(sm + OBQ);

    const int tid = threadIdx.x, lane = tid & 31, wid = tid >> 5;
    const int r = lane >> 2, c2 = lane & 3;
    const uint32_t smb = (uint32_t)__cvta_generic_to_shared(sm);

    // one-time fills (coalesced fp32 reads, fp16 convert)
    for (int i = tid; i < 256 * 128; i += 256) {
        int k = i >> 8, n = i & 255;                  // W1[k][n], n contiguous
        sW1[n * S1 + k] = __float2half_rn(W1[i]);
    }
    for (int i = tid; i < 64 * 256; i += 256) {
        int k = i >> 6, n = i & 63;                   // W2[k][n]
        sW2[n * S2 + k] = __float2half_rn(W2[i]);
    }
    for (int i = tid; i < 64 * 64; i += 256) {
        int k = i >> 6, n = i & 63;                   // Wq[k][n]
        sWq[n * SQ + k] = __float2half_rn(Wq[i]);
    }
    if (tid < 256) sB1[tid] = b1[tid];
    if (tid < 64) { sB2[tid] = b2[tid]; sBq[tid] = bq[tid]; }
    __syncthreads();

    const int lrow = (lane & 7) + ((lane >> 3) & 1) * 8;   // ldmatrix row
    const int lk   = (lane >> 4) * 8;                      // ldmatrix k offset
    const uint32_t pXs = smb + OPX, pHs = smb + OPH;
    const int oc = (wid << 3) + (c2 << 1);
    const float b2v0 = sB2[oc], b2v1 = sB2[oc + 1];
    const float bqv0 = sBq[oc], bqv1 = sBq[oc + 1];
    float b1v[4][2];
#pragma unroll
    for (int nt = 0; nt < 4; nt++) {
        int n0 = (wid << 5) + (nt << 3) + (c2 << 1);
        b1v[nt][0] = sB1[n0]; b1v[nt][1] = sB1[n0 + 1];
    }

    // prologue: load first tile's X into regs
    float xr[32];
    {
        int t0 = blockIdx.x;
        if (t0 < NTILES) {
            const size_t row0 = (size_t)t0 * 64;
#pragma unroll
            for (int i = 0; i < 8; i++) {
                int e = i * 256 + tid;
                int row = e >> 5, kk = (e & 31) * 4;
                const float* src = (kk < 64) ? (A + (row0 + row) * 64 + kk)
                                             : (Bm + (row0 + row) * 64 + kk - 64);
                float4 v = *(const float4*)src;
                xr[4 * i] = v.x; xr[4 * i + 1] = v.y;
                xr[4 * i + 2] = v.z; xr[4 * i + 3] = v.w;
            }
        }
    }

    for (int t = blockIdx.x; t < NTILES; t += gridDim.x) {
        const size_t row0 = (size_t)t * 64;

        // ---- store X plane from prefetched regs ----
#pragma unroll
        for (int i = 0; i < 8; i++) {
            int e = i * 256 + tid;
            int row = e >> 5, kk = (e & 31) * 4;
            *(uint2*)(pX + row * S1 + kk) =
                make_uint2(pack2h(xr[4 * i], xr[4 * i + 1]),
                           pack2h(xr[4 * i + 2], xr[4 * i + 3]));
        }
        __syncthreads();                                  // (a)

        // prefetch q for this tile (consumed after stage1)
        float qr[16];
#pragma unroll
        for (int i = 0; i < 4; i++) {
            int e = i * 256 + tid;
            int row = e >> 4, kk = (e & 15) * 4;
            float4 v = *(const float4*)(qp + (row0 + row) * 64 + kk);
            qr[4 * i] = v.x; qr[4 * i + 1] = v.y;
            qr[4 * i + 2] = v.z; qr[4 * i + 3] = v.w;
        }

        // ---- stage 1: acc = X @ W1h ----
        float acc[4][4][4];
#pragma unroll
        for (int mt = 0; mt < 4; mt++)
#pragma unroll
            for (int nt = 0; nt < 4; nt++)
#pragma unroll
                for (int i = 0; i < 4; i++) acc[mt][nt][i] = 0.f;
#pragma unroll
        for (int ks = 0; ks < 8; ks++) {
            const int k0 = ks * 16;
            uint32_t ah[4][4];
#pragma unroll
            for (int mt = 0; mt < 4; mt++) {
                uint32_t off = (uint32_t)(((16 * mt + lrow) * S1 + k0 + lk) * 2);
                ldsm4(ah[mt], pXs + off);
            }
#pragma unroll
            for (int nt = 0; nt < 4; nt++) {
                int n = (wid << 5) + (nt << 3) + r;
                uint32_t wb0 = *(const uint32_t*)(sW1 + n * S1 + k0 + (c2 << 1));
                uint32_t wb1 = *(const uint32_t*)(sW1 + n * S1 + k0 + 8 + (c2 << 1));
#pragma unroll
                for (int mt = 0; mt < 4; mt++)
                    mma16816h(acc[mt][nt], ah[mt], wb0, wb1);
            }
        }
        __syncthreads();                                  // (b)

        // ---- store H (relu+bias, fp16) + q into dead X plane ----
#pragma unroll
        for (int mt = 0; mt < 4; mt++)
#pragma unroll
            for (int nt = 0; nt < 4; nt++) {
                int cl = (wid << 5) + (nt << 3) + (c2 << 1);
                float h0 = fmaxf(acc[mt][nt][0] + b1v[nt][0], 0.f);
                float h1 = fmaxf(acc[mt][nt][1] + b1v[nt][1], 0.f);
                *(uint32_t*)(pH + (16 * mt + r) * S2 + cl) = pack2h(h0, h1);
                float h2 = fmaxf(acc[mt][nt][2] + b1v[nt][0], 0.f);
                float h3 = fmaxf(acc[mt][nt][3] + b1v[nt][1], 0.f);
                *(uint32_t*)(pH + (16 * mt + 8 + r) * S2 + cl) = pack2h(h2, h3);
            }
#pragma unroll
        for (int i = 0; i < 4; i++) {
            int e = i * 256 + tid;
            int row = e >> 4, kk = (e & 15) * 4;
            *(uint2*)(pX + row * S1 + kk) =
                make_uint2(pack2h(qr[4 * i], qr[4 * i + 1]),
                           pack2h(qr[4 * i + 2], qr[4 * i + 3]));
        }

        // prefetch next tile's X (overlaps stage2/gate MMAs)
        {
            int tn = t + gridDim.x;
            if (tn < NTILES) {
                const size_t rown = (size_t)tn * 64;
#pragma unroll
                for (int i = 0; i < 8; i++) {
                    int e = i * 256 + tid;
                    int row = e >> 5, kk = (e & 31) * 4;
                    const float* src = (kk < 64) ? (A + (rown + row) * 64 + kk)
                                                 : (Bm + (rown + row) * 64 + kk - 64);
                    float4 v = *(const float4*)src;
                    xr[4 * i] = v.x; xr[4 * i + 1] = v.y;
                    xr[4 * i + 2] = v.z; xr[4 * i + 3] = v.w;
                }
            }
        }
        __syncthreads();                                  // (c)

        // ---- stage 2: M = H @ W2h (K=256, single pass) ----
        float acc2[4][4];
#pragma unroll
        for (int mt = 0; mt < 4; mt++)
#pragma unroll
            for (int i = 0; i < 4; i++) acc2[mt][i] = 0.f;
#pragma unroll
        for (int ks = 0; ks < 16; ks++) {
            const int k0 = ks * 16;
            uint32_t ah[4][4];
#pragma unroll
            for (int mt = 0; mt < 4; mt++) {
                uint32_t off = (uint32_t)(((16 * mt + lrow) * S2 + k0 + lk) * 2);
                ldsm4(ah[mt], pHs + off);
            }
            int n = (wid << 3) + r;
            uint32_t wb0 = *(const uint32_t*)(sW2 + n * S2 + k0 + (c2 << 1));
            uint32_t wb1 = *(const uint32_t*)(sW2 + n * S2 + k0 + 8 + (c2 << 1));
#pragma unroll
            for (int mt = 0; mt < 4; mt++)
                mma16816h(acc2[mt], ah[mt], wb0, wb1);
        }

        // ---- gate: G = q @ Wqh ----
        float accg[4][4];
#pragma unroll
        for (int mt = 0; mt < 4; mt++)
#pragma unroll
            for (int i = 0; i < 4; i++) accg[mt][i] = 0.f;
#pragma unroll
        for (int ks = 0; ks < 4; ks++) {
            const int k0 = ks * 16;
            uint32_t ah[4][4];
#pragma unroll
            for (int mt = 0; mt < 4; mt++) {
                uint32_t off = (uint32_t)(((16 * mt + lrow) * S1 + k0 + lk) * 2);
                ldsm4(ah[mt], pXs + off);
            }
            int n = (wid << 3) + r;
            uint32_t wb0 = *(const uint32_t*)(sWq + n * SQ + k0 + (c2 << 1));
            uint32_t wb1 = *(const uint32_t*)(sWq + n * SQ + k0 + 8 + (c2 << 1));
#pragma unroll
            for (int mt = 0; mt < 4; mt++)
                mma16816h(accg[mt], ah[mt], wb0, wb1);
        }

        // ---- epilogue ----
#pragma unroll
        for (int mt = 0; mt < 4; mt++) {
            int row = 16 * mt + r;
            float m0 = acc2[mt][0] + b2v0, m1 = acc2[mt][1] + b2v1;
            float sp0 = fmaxf(m0, 0.f) + log1pf(expf(-fabsf(m0)));
            float sp1 = fmaxf(m1, 0.f) + log1pf(expf(-fabsf(m1)));
            float g0 = tanhf(accg[mt][0] + bqv0), g1 = tanhf(accg[mt][1] + bqv1);
            *(float2*)&g_mu[(row0 + row) * 64 + oc] =
                make_float2(sp0 * (1.f + 0.5f * g0), sp1 * (1.f + 0.5f * g1));
            float m2 = acc2[mt][2] + b2v0, m3 = acc2[mt][3] + b2v1;
            float sp2 = fmaxf(m2, 0.f) + log1pf(expf(-fabsf(m2)));
            float sp3 = fmaxf(m3, 0.f) + log1pf(expf(-fabsf(m3)));
            float g2 = tanhf(accg[mt][2] + bqv0), g3 = tanhf(accg[mt][3] + bqv1);
            *(float2*)&g_mu[(row0 + row + 8) * 64 + oc] =
                make_float2(sp2 * (1.f + 0.5f * g2), sp3 * (1.f + 0.5f * g3));
        }
        __syncthreads();                                  // (d)
    }
}

// ---------------------------------------------------------------------------
// Iteration kernel: 10 rows/thread, TL=64 interior, halo 8, 2 blocks/SM.
// smooth(x)[l] = 0.9*x[l] + 0.05*(x[l-1]+x[l+1]);  D scaled by (1-0.3*mu).
// ---------------------------------------------------------------------------
__global__ void __launch_bounds__(512, 2) iter_kernel(
        const float* __restrict__ A, const float* __restrict__ Bm,
        float* __restrict__ hA, float* __restrict__ hB)
{
    __shared__ float sme[2][4][8][64];
    const int tid = threadIdx.x;
    const int c = tid & 63;
    const int j = tid >> 6;
    const int b = blockIdx.y;
    const int lbase = blockIdx.x * 64 - 8;
    const size_t base = ((size_t)b << 13);

    float D[10], S[10], MU[10];
#pragma unroll
    for (int rr = 0; rr < 10; rr++) {
        int l = (lbase + j * 10 + rr) & (LEN - 1);
        size_t g = (base + l) * 64 + c;
        float a = A[g], bb = Bm[g];
        D[rr] = a - bb;
        S[rr] = a + bb;
        MU[rr] = g_mu[g];
    }

#pragma unroll
    for (int k = 0; k < 6; k++) {
        const int p = k & 1;
        sme[p][0][j][c] = (1.f - 0.3f * MU[0]) * D[0];
        sme[p][1][j][c] = (1.f - 0.3f * MU[9]) * D[9];
        sme[p][2][j][c] = S[0];
        sme[p][3][j][c] = S[9];
        __syncthreads();
        float gylo = (j > 0) ? sme[p][1][j - 1][c] : 0.f;
        float gyhi = (j < 7) ? sme[p][0][j + 1][c] : 0.f;
        float gslo = (j > 0) ? sme[p][3][j - 1][c] : 0.f;
        float gshi = (j < 7) ? sme[p][2][j + 1][c] : 0.f;

        float yprev = gylo, sprev = gslo;
#pragma unroll
        for (int rr = 0; rr < 10; rr++) {
            float ycur  = (1.f - 0.3f * MU[rr]) * D[rr];
            float ynext = (rr < 9) ? (1.f - 0.3f * MU[rr + 1]) * D[rr + 1] : gyhi;
            float scur  = S[rr];
            float snext = (rr < 9) ? S[rr + 1] : gshi;
            D[rr] = 0.9f * ycur + 0.05f * (yprev + ynext);
            S[rr] = 0.9f * scur + 0.05f * (sprev + snext);
            yprev = ycur;
            sprev = scur;
        }
    }

    float esum = 0.f;
#pragma unroll
    for (int rr = 0; rr < 10; rr++) {
        int gidx = j * 10 + rr;
        if (gidx >= 8 && gidx < 72) {
            int l = blockIdx.x * 64 + (gidx - 8);
            size_t g = (base + l) * 64 + c;
            hA[g] = 0.5f * (S[rr] + D[rr]);
            hB[g] = 0.5f * (S[rr] - D[rr]);
            esum += 0.5f * MU[rr] * D[rr] * D[rr];
        }
    }

#pragma unroll
    for (int o = 16; o > 0; o >>= 1)
        esum += __shfl_xor_sync(0xffffffffu, esum, o);
    __shared__ float sred[16];
    if ((tid & 31) == 0) sred[tid >> 5] = esum;
    __syncthreads();
    if (tid == 0) {
        float tt = 0.f;
#pragma unroll
        for (int w = 0; w < 16; w++) tt += sred[w];
        g_epart[b * 128 + blockIdx.x] = tt;
    }
}

// ---------------------------------------------------------------------------
__global__ void __launch_bounds__(128) energy_reduce(float* __restrict__ energy)
{
    const int b = blockIdx.x;
    const int tid = threadIdx.x;
    float v = g_epart[b * 128 + tid];
#pragma unroll
    for (int o = 16; o > 0; o >>= 1)
        v += __shfl_xor_sync(0xffffffffu, v, o);
    __shared__ float s[4];
    if ((tid & 31) == 0) s[tid >> 5] = v;
    __syncthreads();
    if (tid == 0) energy[b] = s[0] + s[1] + s[2] + s[3];
}

// ---------------------------------------------------------------------------
extern "C" void kernel_launch(void* const* d_in, const int* in_sizes, int n_in,
                              void* d_out, int out_size)
{
    const float* A  = (const float*)d_in[0];
    const float* Bm = (const float*)d_in[1];
    const float* q  = (const float*)d_in[2];
    const float* W1 = (const float*)d_in[3];
    const float* b1 = (const float*)d_in[4];
    const float* W2 = (const float*)d_in[5];
    const float* b2 = (const float*)d_in[6];
    const float* Wq = (const float*)d_in[7];
    const float* bq = (const float*)d_in[8];

    float* out = (float*)d_out;
    float* hA = out;
    float* hB = out + (size_t)ROWS * 64;
    float* en = out + 2 * (size_t)ROWS * 64;

    static int attr_set = 0;
    if (!attr_set) {
        cudaFuncSetAttribute(mu_kernel,
            cudaFuncAttributeMaxDynamicSharedMemorySize, SMEM_MU);
        attr_set = 1;
    }
    mu_kernel<<<MUGRID, 256, SMEM_MU>>>(A, Bm, q, W1, b1, W2, b2, Wq, bq);

    iter_kernel<<<dim3(LEN / 64, BSZ), 512>>>(A, Bm, hA, hB);

    energy_reduce<<<BSZ, 128>>>(en);
}

// round 13
// speedup vs baseline: 8.7531x; 1.0343x over previous
#include <cuda_runtime.h>
#include <cuda_fp16.h>
#include <math.h>
#include <stdint.h>

#define BSZ 32
#define LEN 8192
#define ROWS (BSZ*LEN)
#define NTILES (ROWS/64)     // 4096 tiles of 64 rows
#define MUGRID 148

// fp16-element strides (all == 4 mod 32 words -> conflict-free)
#define S1 136
#define S2 264
#define SQ 72
// smem byte offsets
#define OW2  69632
#define OWQ  103424
#define OPX  112640
#define OPH  130048
#define OB1  163840
#define OB2  164864
#define OBQ  165120
#define SMEM_MU 165376

__device__ float g_mu[(size_t)ROWS * 64];
__device__ float g_epart[BSZ * 128];

// ---------------------------------------------------------------------------
__device__ __forceinline__ void mma16816h(float* c, const uint32_t* a,
                                          uint32_t b0, uint32_t b1)
{
    asm volatile(
        "mma.sync.aligned.m16n8k16.row.col.f32.f16.f16.f32 "
        "{%0,%1,%2,%3},{%4,%5,%6,%7},{%8,%9},{%0,%1,%2,%3};\n"
        : "+f"(c[0]), "+f"(c[1]), "+f"(c[2]), "+f"(c[3])
        : "r"(a[0]), "r"(a[1]), "r"(a[2]), "r"(a[3]), "r"(b0), "r"(b1));
}

__device__ __forceinline__ void ldsm4(uint32_t* d, uint32_t addr)
{
    asm volatile("ldmatrix.sync.aligned.m8n8.x4.shared.b16 {%0,%1,%2,%3}, [%4];"
        : "=r"(d[0]), "=r"(d[1]), "=r"(d[2]), "=r"(d[3]) : "r"(addr));
}

__device__ __forceinline__ uint32_t pack2h(float x0, float x1)
{
    __half2 h = __floats2half2_rn(x0, x1);
    return *(uint32_t*)&h;
}

// ---------------------------------------------------------------------------
// Persistent mu kernel: 148 CTAs x 512 thr (16 warps = 4/SMSP), 64-row tiles.
//   H = relu([A;B] @ W1h + b1); M = H @ W2h + b2; G = q @ Wqh + bq
//   mu = softplus(M) * (1 + 0.5*tanh(G))
// Stage1 warp split 2m x 8n (32 rows x 32 cols); stage2/gate 2m x 8n
// (32 rows x 8 cols). Prefetch q during stage1, next X during stage2.
// ---------------------------------------------------------------------------
__global__ void __launch_bounds__(512, 1) mu_kernel(
        const float* __restrict__ A, const float* __restrict__ Bm,
        const float* __restrict__ qp,
        const float* __restrict__ W1, const float* __restrict__ b1,
        const float* __restrict__ W2, const float* __restrict__ b2,
        const float* __restrict__ Wq, const float* __restrict__ bq)
{
    extern __shared__ char sm[];
    __half* sW1 = (__half*)sm;
    __half* sW2 = (__half*)(sm + OW2);
    __half* sWq = (__half*)(sm + OWQ);
    __half* pX  = (__half*)(sm + OPX);
    __half* pH  = (__half*)(sm + OPH);
    float* sB1 = (float*)(sm + OB1);
    float* sB2 = (float*)(sm + OB2);
    float* sBq = (float*)(sm + OBQ);

    const int tid = threadIdx.x, lane = tid & 31, wid = tid >> 5;
    const int wm = wid & 1, wn = wid >> 1;            // 2 m-warps x 8 n-warps
    const int r = lane >> 2, c2 = lane & 3;
    const uint32_t smb = (uint32_t)__cvta_generic_to_shared(sm);

    // one-time fills (coalesced fp32 reads, fp16 convert)
    for (int i = tid; i < 256 * 128; i += 512) {
        int k = i >> 8, n = i & 255;                  // W1[k][n]
        sW1[n * S1 + k] = __float2half_rn(W1[i]);
    }
    for (int i = tid; i < 64 * 256; i += 512) {
        int k = i >> 6, n = i & 63;                   // W2[k][n]
        sW2[n * S2 + k] = __float2half_rn(W2[i]);
    }
    for (int i = tid; i < 64 * 64; i += 512) {
        int k = i >> 6, n = i & 63;                   // Wq[k][n]
        sWq[n * SQ + k] = __float2half_rn(Wq[i]);
    }
    if (tid < 256) sB1[tid] = b1[tid];
    if (tid < 64) { sB2[tid] = b2[tid]; sBq[tid] = bq[tid]; }
    __syncthreads();

    const int lrow = (lane & 7) + ((lane >> 3) & 1) * 8;   // ldmatrix row
    const int lk   = (lane >> 4) * 8;                      // ldmatrix k offset
    const uint32_t pXs = smb + OPX, pHs = smb + OPH;
    const int oc = (wn << 3) + (c2 << 1);                  // stage2/gate out col
    const float b2v0 = sB2[oc], b2v1 = sB2[oc + 1];
    const float bqv0 = sBq[oc], bqv1 = sBq[oc + 1];
    float b1v[4][2];
#pragma unroll
    for (int nt = 0; nt < 4; nt++) {
        int n0 = (wn << 5) + (nt << 3) + (c2 << 1);
        b1v[nt][0] = sB1[n0]; b1v[nt][1] = sB1[n0 + 1];
    }

    // prologue: load first tile's X, packed to half2 immediately (8 regs)
    uint32_t xr[8];
    {
        int t0 = blockIdx.x;
        if (t0 < NTILES) {
            const size_t row0 = (size_t)t0 * 64;
#pragma unroll
            for (int i = 0; i < 4; i++) {
                int e = i * 512 + tid;
                int row = e >> 5, kk = (e & 31) * 4;
                const float* src = (kk < 64) ? (A + (row0 + row) * 64 + kk)
                                             : (Bm + (row0 + row) * 64 + kk - 64);
                float4 v = *(const float4*)src;
                xr[2 * i]     = pack2h(v.x, v.y);
                xr[2 * i + 1] = pack2h(v.z, v.w);
            }
        }
    }

    for (int t = blockIdx.x; t < NTILES; t += gridDim.x) {
        const size_t row0 = (size_t)t * 64;

        // ---- store X plane from prefetched packed regs ----
#pragma unroll
        for (int i = 0; i < 4; i++) {
            int e = i * 512 + tid;
            int row = e >> 5, kk = (e & 31) * 4;
            *(uint2*)(pX + row * S1 + kk) = make_uint2(xr[2 * i], xr[2 * i + 1]);
        }
        __syncthreads();                                  // (a)

        // prefetch q for this tile (packed, 4 regs)
        uint32_t qr[4];
#pragma unroll
        for (int i = 0; i < 2; i++) {
            int e = i * 512 + tid;
            int row = e >> 4, kk = (e & 15) * 4;
            float4 v = *(const float4*)(qp + (row0 + row) * 64 + kk);
            qr[2 * i]     = pack2h(v.x, v.y);
            qr[2 * i + 1] = pack2h(v.z, v.w);
        }

        // ---- stage 1: acc = X @ W1h (warp: 32 rows x 32 cols) ----
        float acc[2][4][4];
#pragma unroll
        for (int mt = 0; mt < 2; mt++)
#pragma unroll
            for (int nt = 0; nt < 4; nt++)
#pragma unroll
                for (int i = 0; i < 4; i++) acc[mt][nt][i] = 0.f;
#pragma unroll
        for (int ks = 0; ks < 8; ks++) {
            const int k0 = ks * 16;
            uint32_t ah[2][4];
#pragma unroll
            for (int mt = 0; mt < 2; mt++) {
                uint32_t off = (uint32_t)((((wm << 5) + 16 * mt + lrow) * S1 + k0 + lk) * 2);
                ldsm4(ah[mt], pXs + off);
            }
#pragma unroll
            for (int nt = 0; nt < 4; nt++) {
                int n = (wn << 5) + (nt << 3) + r;
                uint32_t wb0 = *(const uint32_t*)(sW1 + n * S1 + k0 + (c2 << 1));
                uint32_t wb1 = *(const uint32_t*)(sW1 + n * S1 + k0 + 8 + (c2 << 1));
#pragma unroll
                for (int mt = 0; mt < 2; mt++)
                    mma16816h(acc[mt][nt], ah[mt], wb0, wb1);
            }
        }
        __syncthreads();                                  // (b)

        // ---- store H (relu+bias, fp16) + q into dead X plane ----
#pragma unroll
        for (int mt = 0; mt < 2; mt++)
#pragma unroll
            for (int nt = 0; nt < 4; nt++) {
                int cl = (wn << 5) + (nt << 3) + (c2 << 1);
                int rb = (wm << 5) + 16 * mt;
                float h0 = fmaxf(acc[mt][nt][0] + b1v[nt][0], 0.f);
                float h1 = fmaxf(acc[mt][nt][1] + b1v[nt][1], 0.f);
                *(uint32_t*)(pH + (rb + r) * S2 + cl) = pack2h(h0, h1);
                float h2 = fmaxf(acc[mt][nt][2] + b1v[nt][0], 0.f);
                float h3 = fmaxf(acc[mt][nt][3] + b1v[nt][1], 0.f);
                *(uint32_t*)(pH + (rb + 8 + r) * S2 + cl) = pack2h(h2, h3);
            }
#pragma unroll
        for (int i = 0; i < 2; i++) {
            int e = i * 512 + tid;
            int row = e >> 4, kk = (e & 15) * 4;
            *(uint2*)(pX + row * S1 + kk) = make_uint2(qr[2 * i], qr[2 * i + 1]);
        }

        // prefetch next tile's X (overlaps stage2/gate MMAs)
        {
            int tn = t + gridDim.x;
            if (tn < NTILES) {
                const size_t rown = (size_t)tn * 64;
#pragma unroll
                for (int i = 0; i < 4; i++) {
                    int e = i * 512 + tid;
                    int row = e >> 5, kk = (e & 31) * 4;
                    const float* src = (kk < 64) ? (A + (rown + row) * 64 + kk)
                                                 : (Bm + (rown + row) * 64 + kk - 64);
                    float4 v = *(const float4*)src;
                    xr[2 * i]     = pack2h(v.x, v.y);
                    xr[2 * i + 1] = pack2h(v.z, v.w);
                }
            }
        }
        __syncthreads();                                  // (c)

        // ---- stage 2: M = H @ W2h (warp: 32 rows x 8 cols, K=256) ----
        float acc2[2][4];
#pragma unroll
        for (int mt = 0; mt < 2; mt++)
#pragma unroll
            for (int i = 0; i < 4; i++) acc2[mt][i] = 0.f;
#pragma unroll
        for (int ks = 0; ks < 16; ks++) {
            const int k0 = ks * 16;
            uint32_t ah[2][4];
#pragma unroll
            for (int mt = 0; mt < 2; mt++) {
                uint32_t off = (uint32_t)((((wm << 5) + 16 * mt + lrow) * S2 + k0 + lk) * 2);
                ldsm4(ah[mt], pHs + off);
            }
            int n = (wn << 3) + r;
            uint32_t wb0 = *(const uint32_t*)(sW2 + n * S2 + k0 + (c2 << 1));
            uint32_t wb1 = *(const uint32_t*)(sW2 + n * S2 + k0 + 8 + (c2 << 1));
#pragma unroll
            for (int mt = 0; mt < 2; mt++)
                mma16816h(acc2[mt], ah[mt], wb0, wb1);
        }

        // ---- gate: G = q @ Wqh (K=64) ----
        float accg[2][4];
#pragma unroll
        for (int mt = 0; mt < 2; mt++)
#pragma unroll
            for (int i = 0; i < 4; i++) accg[mt][i] = 0.f;
#pragma unroll
        for (int ks = 0; ks < 4; ks++) {
            const int k0 = ks * 16;
            uint32_t ah[2][4];
#pragma unroll
            for (int mt = 0; mt < 2; mt++) {
                uint32_t off = (uint32_t)((((wm << 5) + 16 * mt + lrow) * S1 + k0 + lk) * 2);
                ldsm4(ah[mt], pXs + off);
            }
            int n = (wn << 3) + r;
            uint32_t wb0 = *(const uint32_t*)(sWq + n * SQ + k0 + (c2 << 1));
            uint32_t wb1 = *(const uint32_t*)(sWq + n * SQ + k0 + 8 + (c2 << 1));
#pragma unroll
            for (int mt = 0; mt < 2; mt++)
                mma16816h(accg[mt], ah[mt], wb0, wb1);
        }

        // ---- epilogue ----
#pragma unroll
        for (int mt = 0; mt < 2; mt++) {
            int row = (wm << 5) + 16 * mt + r;
            float m0 = acc2[mt][0] + b2v0, m1 = acc2[mt][1] + b2v1;
            float sp0 = fmaxf(m0, 0.f) + log1pf(expf(-fabsf(m0)));
            float sp1 = fmaxf(m1, 0.f) + log1pf(expf(-fabsf(m1)));
            float g0 = tanhf(accg[mt][0] + bqv0), g1 = tanhf(accg[mt][1] + bqv1);
            *(float2*)&g_mu[(row0 + row) * 64 + oc] =
                make_float2(sp0 * (1.f + 0.5f * g0), sp1 * (1.f + 0.5f * g1));
            float m2 = acc2[mt][2] + b2v0, m3 = acc2[mt][3] + b2v1;
            float sp2 = fmaxf(m2, 0.f) + log1pf(expf(-fabsf(m2)));
            float sp3 = fmaxf(m3, 0.f) + log1pf(expf(-fabsf(m3)));
            float g2 = tanhf(accg[mt][2] + bqv0), g3 = tanhf(accg[mt][3] + bqv1);
            *(float2*)&g_mu[(row0 + row + 8) * 64 + oc] =
                make_float2(sp2 * (1.f + 0.5f * g2), sp3 * (1.f + 0.5f * g3));
        }
        __syncthreads();                                  // (d)
    }
}

// ---------------------------------------------------------------------------
// Iteration kernel: 10 rows/thread, TL=64 interior, halo 8, 2 blocks/SM.
// smooth(x)[l] = 0.9*x[l] + 0.05*(x[l-1]+x[l+1]);  D scaled by (1-0.3*mu).
// ---------------------------------------------------------------------------
__global__ void __launch_bounds__(512, 2) iter_kernel(
        const float* __restrict__ A, const float* __restrict__ Bm,
        float* __restrict__ hA, float* __restrict__ hB)
{
    __shared__ float sme[2][4][8][64];
    const int tid = threadIdx.x;
    const int c = tid & 63;
    const int j = tid >> 6;
    const int b = blockIdx.y;
    const int lbase = blockIdx.x * 64 - 8;
    const size_t base = ((size_t)b << 13);

    float D[10], S[10], MU[10];
#pragma unroll
    for (int rr = 0; rr < 10; rr++) {
        int l = (lbase + j * 10 + rr) & (LEN - 1);
        size_t g = (base + l) * 64 + c;
        float a = A[g], bb = Bm[g];
        D[rr] = a - bb;
        S[rr] = a + bb;
        MU[rr] = g_mu[g];
    }

#pragma unroll
    for (int k = 0; k < 6; k++) {
        const int p = k & 1;
        sme[p][0][j][c] = (1.f - 0.3f * MU[0]) * D[0];
        sme[p][1][j][c] = (1.f - 0.3f * MU[9]) * D[9];
        sme[p][2][j][c] = S[0];
        sme[p][3][j][c] = S[9];
        __syncthreads();
        float gylo = (j > 0) ? sme[p][1][j - 1][c] : 0.f;
        float gyhi = (j < 7) ? sme[p][0][j + 1][c] : 0.f;
        float gslo = (j > 0) ? sme[p][3][j - 1][c] : 0.f;
        float gshi = (j < 7) ? sme[p][2][j + 1][c] : 0.f;

        float yprev = gylo, sprev = gslo;
#pragma unroll
        for (int rr = 0; rr < 10; rr++) {
            float ycur  = (1.f - 0.3f * MU[rr]) * D[rr];
            float ynext = (rr < 9) ? (1.f - 0.3f * MU[rr + 1]) * D[rr + 1] : gyhi;
            float scur  = S[rr];
            float snext = (rr < 9) ? S[rr + 1] : gshi;
            D[rr] = 0.9f * ycur + 0.05f * (yprev + ynext);
            S[rr] = 0.9f * scur + 0.05f * (sprev + snext);
            yprev = ycur;
            sprev = scur;
        }
    }

    float esum = 0.f;
#pragma unroll
    for (int rr = 0; rr < 10; rr++) {
        int gidx = j * 10 + rr;
        if (gidx >= 8 && gidx < 72) {
            int l = blockIdx.x * 64 + (gidx - 8);
            size_t g = (base + l) * 64 + c;
            hA[g] = 0.5f * (S[rr] + D[rr]);
            hB[g] = 0.5f * (S[rr] - D[rr]);
            esum += 0.5f * MU[rr] * D[rr] * D[rr];
        }
    }

#pragma unroll
    for (int o = 16; o > 0; o >>= 1)
        esum += __shfl_xor_sync(0xffffffffu, esum, o);
    __shared__ float sred[16];
    if ((tid & 31) == 0) sred[tid >> 5] = esum;
    __syncthreads();
    if (tid == 0) {
        float tt = 0.f;
#pragma unroll
        for (int w = 0; w < 16; w++) tt += sred[w];
        g_epart[b * 128 + blockIdx.x] = tt;
    }
}

// ---------------------------------------------------------------------------
__global__ void __launch_bounds__(128) energy_reduce(float* __restrict__ energy)
{
    const int b = blockIdx.x;
    const int tid = threadIdx.x;
    float v = g_epart[b * 128 + tid];
#pragma unroll
    for (int o = 16; o > 0; o >>= 1)
        v += __shfl_xor_sync(0xffffffffu, v, o);
    __shared__ float s[4];
    if ((tid & 31) == 0) s[tid >> 5] = v;
    __syncthreads();
    if (tid == 0) energy[b] = s[0] + s[1] + s[2] + s[3];
}

// ---------------------------------------------------------------------------
extern "C" void kernel_launch(void* const* d_in, const int* in_sizes, int n_in,
                              void* d_out, int out_size)
{
    const float* A  = (const float*)d_in[0];
    const float* Bm = (const float*)d_in[1];
    const float* q  = (const float*)d_in[2];
    const float* W1 = (const float*)d_in[3];
    const float* b1 = (const float*)d_in[4];
    const float* W2 = (const float*)d_in[5];
    const float* b2 = (const float*)d_in[6];
    const float* Wq = (const float*)d_in[7];
    const float* bq = (const float*)d_in[8];

    float* out = (float*)d_out;
    float* hA = out;
    float* hB = out + (size_t)ROWS * 64;
    float* en = out + 2 * (size_t)ROWS * 64;

    static int attr_set = 0;
    if (!attr_set) {
        cudaFuncSetAttribute(mu_kernel,
            cudaFuncAttributeMaxDynamicSharedMemorySize, SMEM_MU);
        attr_set = 1;
    }
    mu_kernel<<<MUGRID, 512, SMEM_MU>>>(A, Bm, q, W1, b1, W2, b2, Wq, bq);

    iter_kernel<<<dim3(LEN / 64, BSZ), 512>>>(A, Bm, hA, hB);

    energy_reduce<<<BSZ, 128>>>(en);
}

// round 15
// speedup vs baseline: 9.7248x; 1.1110x over previous
#include <cuda_runtime.h>
#include <cuda_fp16.h>
#include <math.h>
#include <stdint.h>

#define BSZ 32
#define LEN 8192
#define ROWS (BSZ*LEN)
#define NTILES (ROWS/64)     // 4096 tiles of 64 rows
#define MUGRID 148

// fp16-element strides (all == 4 mod 32 words -> conflict-free)
#define S1 136
#define S2 264
#define SQ 72
// smem byte offsets
#define OW2  69632
#define OWQ  103424
#define OPX  112640
#define OPH  130048
#define OB1  163840
#define OB2  164864
#define OBQ  165120
#define SMEM_MU 165376

__device__ float g_mu[(size_t)ROWS * 64];
__device__ float g_epart[BSZ * 128];

// ---------------------------------------------------------------------------
__device__ __forceinline__ void mma16816h(float* c, const uint32_t* a,
                                          uint32_t b0, uint32_t b1)
{
    asm volatile(
        "mma.sync.aligned.m16n8k16.row.col.f32.f16.f16.f32 "
        "{%0,%1,%2,%3},{%4,%5,%6,%7},{%8,%9},{%0,%1,%2,%3};\n"
        : "+f"(c[0]), "+f"(c[1]), "+f"(c[2]), "+f"(c[3])
        : "r"(a[0]), "r"(a[1]), "r"(a[2]), "r"(a[3]), "r"(b0), "r"(b1));
}

__device__ __forceinline__ void ldsm4(uint32_t* d, uint32_t addr)
{
    asm volatile("ldmatrix.sync.aligned.m8n8.x4.shared.b16 {%0,%1,%2,%3}, [%4];"
        : "=r"(d[0]), "=r"(d[1]), "=r"(d[2]), "=r"(d[3]) : "r"(addr));
}

__device__ __forceinline__ uint32_t pack2h(float x0, float x1)
{
    __half2 h = __floats2half2_rn(x0, x1);
    return *(uint32_t*)&h;
}

__device__ __forceinline__ float tanh_fast(float x)
{
    float y;
    asm("tanh.approx.f32 %0, %1;" : "=f"(y) : "f"(x));
    return y;
}

__device__ __forceinline__ float softplus_fast(float m)
{
    return fmaxf(m, 0.f) + __logf(1.f + __expf(-fabsf(m)));
}

// ---------------------------------------------------------------------------
// Persistent mu kernel: 148 CTAs x 512 thr, 64-row tiles, fp16 MMA.
//   H = relu([A;B] @ W1h + b1); M = H @ W2h + b2; G = q @ Wqh + bq
//   mu = softplus(M) * (1 + 0.5*tanh(G))
// Stage1: 2m x 8n warps; stage2/gate: 4m x 4n (min smem duplication).
// All B operands via ldmatrix.x4. Prefetch q during stage1, next X in stage2.
// ---------------------------------------------------------------------------
__global__ void __launch_bounds__(512, 1) mu_kernel(
        const float* __restrict__ A, const float* __restrict__ Bm,
        const float* __restrict__ qp,
        const float* __restrict__ W1, const float* __restrict__ b1,
        const float* __restrict__ W2, const float* __restrict__ b2,
        const float* __restrict__ Wq, const float* __restrict__ bq)
{
    extern __shared__ char sm[];
    __half* sW1 = (__half*)sm;
    __half* sW2 = (__half*)(sm + OW2);
    __half* sWq = (__half*)(sm + OWQ);
    __half* pX  = (__half*)(sm + OPX);
    __half* pH  = (__half*)(sm + OPH);
    float* sB1 = (float*)(sm + OB1);
    float* sB2 = (float*)(sm + OB2);
    float* sBq = (float*)(sm + OBQ);

    const int tid = threadIdx.x, lane = tid & 31, wid = tid >> 5;
    const int wm = wid & 1, wn = wid >> 1;            // stage1: 2m x 8n
    const int wm2 = wid & 3, wn2 = wid >> 2;          // stage2/gate: 4m x 4n
    const int r = lane >> 2, c2 = lane & 3;
    const uint32_t smb = (uint32_t)__cvta_generic_to_shared(sm);

    // one-time fills (coalesced fp32 reads, fp16 convert)
    for (int i = tid; i < 256 * 128; i += 512) {
        int k = i >> 8, n = i & 255;                  // W1[k][n]
        sW1[n * S1 + k] = __float2half_rn(W1[i]);
    }
    for (int i = tid; i < 64 * 256; i += 512) {
        int k = i >> 6, n = i & 63;                   // W2[k][n]
        sW2[n * S2 + k] = __float2half_rn(W2[i]);
    }
    for (int i = tid; i < 64 * 64; i += 512) {
        int k = i >> 6, n = i & 63;                   // Wq[k][n]
        sWq[n * SQ + k] = __float2half_rn(Wq[i]);
    }
    if (tid < 256) sB1[tid] = b1[tid];
    if (tid < 64) { sB2[tid] = b2[tid]; sBq[tid] = bq[tid]; }
    __syncthreads();

    // ldmatrix lane->address components
    const int lrow = (lane & 7) + ((lane >> 3) & 1) * 8;   // A-frag pattern
    const int lk   = (lane >> 4) * 8;
    const int brow = (lane & 7) + ((lane >> 4) << 3);      // B-frag pattern:
    const int bk   = ((lane >> 3) & 1) << 3;               // mats n0-7/k0, n0-7/k8, n8-15/k0, n8-15/k8
    const uint32_t pXs = smb + OPX, pHs = smb + OPH;
    const uint32_t sW1s = smb, sW2s = smb + OW2, sWqs = smb + OWQ;

    const int oc = (wn2 << 4) + (c2 << 1);                 // stage2/gate col base
    float b2v[2][2], bqv[2][2];
#pragma unroll
    for (int nt = 0; nt < 2; nt++) {
        b2v[nt][0] = sB2[oc + (nt << 3)]; b2v[nt][1] = sB2[oc + (nt << 3) + 1];
        bqv[nt][0] = sBq[oc + (nt << 3)]; bqv[nt][1] = sBq[oc + (nt << 3) + 1];
    }
    float b1v[4][2];
#pragma unroll
    for (int nt = 0; nt < 4; nt++) {
        int n0 = (wn << 5) + (nt << 3) + (c2 << 1);
        b1v[nt][0] = sB1[n0]; b1v[nt][1] = sB1[n0 + 1];
    }

    // prologue: first tile's X packed to half2 (8 regs)
    uint32_t xr[8];
    {
        int t0 = blockIdx.x;
        if (t0 < NTILES) {
            const size_t row0 = (size_t)t0 * 64;
#pragma unroll
            for (int i = 0; i < 4; i++) {
                int e = i * 512 + tid;
                int row = e >> 5, kk = (e & 31) * 4;
                const float* src = (kk < 64) ? (A + (row0 + row) * 64 + kk)
                                             : (Bm + (row0 + row) * 64 + kk - 64);
                float4 v = *(const float4*)src;
                xr[2 * i]     = pack2h(v.x, v.y);
                xr[2 * i + 1] = pack2h(v.z, v.w);
            }
        }
    }

    for (int t = blockIdx.x; t < NTILES; t += gridDim.x) {
        const size_t row0 = (size_t)t * 64;

        // ---- store X plane ----
#pragma unroll
        for (int i = 0; i < 4; i++) {
            int e = i * 512 + tid;
            int row = e >> 5, kk = (e & 31) * 4;
            *(uint2*)(pX + row * S1 + kk) = make_uint2(xr[2 * i], xr[2 * i + 1]);
        }
        __syncthreads();                                  // (a)

        // prefetch q (packed, 4 regs)
        uint32_t qr[4];
#pragma unroll
        for (int i = 0; i < 2; i++) {
            int e = i * 512 + tid;
            int row = e >> 4, kk = (e & 15) * 4;
            float4 v = *(const float4*)(qp + (row0 + row) * 64 + kk);
            qr[2 * i]     = pack2h(v.x, v.y);
            qr[2 * i + 1] = pack2h(v.z, v.w);
        }

        // ---- stage 1: acc = X @ W1h (warp: 32 rows x 32 cols) ----
        float acc[2][4][4];
#pragma unroll
        for (int mt = 0; mt < 2; mt++)
#pragma unroll
            for (int nt = 0; nt < 4; nt++)
#pragma unroll
                for (int i = 0; i < 4; i++) acc[mt][nt][i] = 0.f;
#pragma unroll
        for (int ks = 0; ks < 8; ks++) {
            const int k0 = ks * 16;
            uint32_t ah[2][4], bw[8];
#pragma unroll
            for (int mt = 0; mt < 2; mt++) {
                uint32_t off = (uint32_t)((((wm << 5) + 16 * mt + lrow) * S1 + k0 + lk) * 2);
                ldsm4(ah[mt], pXs + off);
            }
            ldsm4(bw,     sW1s + (uint32_t)((((wn << 5) + brow) * S1 + k0 + bk) * 2));
            ldsm4(bw + 4, sW1s + (uint32_t)((((wn << 5) + 16 + brow) * S1 + k0 + bk) * 2));
#pragma unroll
            for (int nt = 0; nt < 4; nt++)
#pragma unroll
                for (int mt = 0; mt < 2; mt++)
                    mma16816h(acc[mt][nt], ah[mt], bw[2 * nt], bw[2 * nt + 1]);
        }
        __syncthreads();                                  // (b)

        // ---- store H (relu+bias, fp16) + q into dead X plane ----
#pragma unroll
        for (int mt = 0; mt < 2; mt++)
#pragma unroll
            for (int nt = 0; nt < 4; nt++) {
                int cl = (wn << 5) + (nt << 3) + (c2 << 1);
                int rb = (wm << 5) + 16 * mt;
                float h0 = fmaxf(acc[mt][nt][0] + b1v[nt][0], 0.f);
                float h1 = fmaxf(acc[mt][nt][1] + b1v[nt][1], 0.f);
                *(uint32_t*)(pH + (rb + r) * S2 + cl) = pack2h(h0, h1);
                float h2 = fmaxf(acc[mt][nt][2] + b1v[nt][0], 0.f);
                float h3 = fmaxf(acc[mt][nt][3] + b1v[nt][1], 0.f);
                *(uint32_t*)(pH + (rb + 8 + r) * S2 + cl) = pack2h(h2, h3);
            }
#pragma unroll
        for (int i = 0; i < 2; i++) {
            int e = i * 512 + tid;
            int row = e >> 4, kk = (e & 15) * 4;
            *(uint2*)(pX + row * S1 + kk) = make_uint2(qr[2 * i], qr[2 * i + 1]);
        }

        // prefetch next tile's X (overlaps stage2/gate MMAs)
        {
            int tn = t + gridDim.x;
            if (tn < NTILES) {
                const size_t rown = (size_t)tn * 64;
#pragma unroll
                for (int i = 0; i < 4; i++) {
                    int e = i * 512 + tid;
                    int row = e >> 5, kk = (e & 31) * 4;
                    const float* src = (kk < 64) ? (A + (rown + row) * 64 + kk)
                                                 : (Bm + (rown + row) * 64 + kk - 64);
                    float4 v = *(const float4*)src;
                    xr[2 * i]     = pack2h(v.x, v.y);
                    xr[2 * i + 1] = pack2h(v.z, v.w);
                }
            }
        }
        __syncthreads();                                  // (c)

        // ---- stage 2: M = H @ W2h (warp: 16 rows x 16 cols, K=256) ----
        float acc2[2][4];
#pragma unroll
        for (int nt = 0; nt < 2; nt++)
#pragma unroll
            for (int i = 0; i < 4; i++) acc2[nt][i] = 0.f;
#pragma unroll
        for (int ks = 0; ks < 16; ks++) {
            const int k0 = ks * 16;
            uint32_t ah[4], bw[4];
            ldsm4(ah, pHs + (uint32_t)((((wm2 << 4) + lrow) * S2 + k0 + lk) * 2));
            ldsm4(bw, sW2s + (uint32_t)((((wn2 << 4) + brow) * S2 + k0 + bk) * 2));
            mma16816h(acc2[0], ah, bw[0], bw[1]);
            mma16816h(acc2[1], ah, bw[2], bw[3]);
        }

        // ---- gate: G = q @ Wqh (warp: 16 rows x 16 cols, K=64) ----
        float accg[2][4];
#pragma unroll
        for (int nt = 0; nt < 2; nt++)
#pragma unroll
            for (int i = 0; i < 4; i++) accg[nt][i] = 0.f;
#pragma unroll
        for (int ks = 0; ks < 4; ks++) {
            const int k0 = ks * 16;
            uint32_t ah[4], bw[4];
            ldsm4(ah, pXs + (uint32_t)((((wm2 << 4) + lrow) * S1 + k0 + lk) * 2));
            ldsm4(bw, sWqs + (uint32_t)((((wn2 << 4) + brow) * SQ + k0 + bk) * 2));
            mma16816h(accg[0], ah, bw[0], bw[1]);
            mma16816h(accg[1], ah, bw[2], bw[3]);
        }

        // ---- epilogue: mu = softplus(M+b2) * (1 + 0.5*tanh(G+bq)) ----
#pragma unroll
        for (int nt = 0; nt < 2; nt++) {
            int col = oc + (nt << 3);
            int row = (wm2 << 4) + r;
            float m0 = acc2[nt][0] + b2v[nt][0], m1 = acc2[nt][1] + b2v[nt][1];
            float g0 = tanh_fast(accg[nt][0] + bqv[nt][0]);
            float g1 = tanh_fast(accg[nt][1] + bqv[nt][1]);
            *(float2*)&g_mu[(row0 + row) * 64 + col] =
                make_float2(softplus_fast(m0) * (1.f + 0.5f * g0),
                            softplus_fast(m1) * (1.f + 0.5f * g1));
            float m2 = acc2[nt][2] + b2v[nt][0], m3 = acc2[nt][3] + b2v[nt][1];
            float g2 = tanh_fast(accg[nt][2] + bqv[nt][0]);
            float g3 = tanh_fast(accg[nt][3] + bqv[nt][1]);
            *(float2*)&g_mu[(row0 + row + 8) * 64 + col] =
                make_float2(softplus_fast(m2) * (1.f + 0.5f * g2),
                            softplus_fast(m3) * (1.f + 0.5f * g3));
        }
        __syncthreads();                                  // (d)
    }
}

// ---------------------------------------------------------------------------
// Iteration kernel: 10 rows/thread, TL=64 interior, halo 8, 2 blocks/SM.
// smooth(x)[l] = 0.9*x[l] + 0.05*(x[l-1]+x[l+1]);  D scaled by (1-0.3*mu).
// ---------------------------------------------------------------------------
__global__ void __launch_bounds__(512, 2) iter_kernel(
        const float* __restrict__ A, const float* __restrict__ Bm,
        float* __restrict__ hA, float* __restrict__ hB)
{
    __shared__ float sme[2][4][8][64];
    const int tid = threadIdx.x;
    const int c = tid & 63;
    const int j = tid >> 6;
    const int b = blockIdx.y;
    const int lbase = blockIdx.x * 64 - 8;
    const size_t base = ((size_t)b << 13);

    float D[10], S[10], MU[10];
#pragma unroll
    for (int rr = 0; rr < 10; rr++) {
        int l = (lbase + j * 10 + rr) & (LEN - 1);
        size_t g = (base + l) * 64 + c;
        float a = A[g], bb = Bm[g];
        D[rr] = a - bb;
        S[rr] = a + bb;
        MU[rr] = g_mu[g];
    }

#pragma unroll
    for (int k = 0; k < 6; k++) {
        const int p = k & 1;
        sme[p][0][j][c] = (1.f - 0.3f * MU[0]) * D[0];
        sme[p][1][j][c] = (1.f - 0.3f * MU[9]) * D[9];
        sme[p][2][j][c] = S[0];
        sme[p][3][j][c] = S[9];
        __syncthreads();
        float gylo = (j > 0) ? sme[p][1][j - 1][c] : 0.f;
        float gyhi = (j < 7) ? sme[p][0][j + 1][c] : 0.f;
        float gslo = (j > 0) ? sme[p][3][j - 1][c] : 0.f;
        float gshi = (j < 7) ? sme[p][2][j + 1][c] : 0.f;

        float yprev = gylo, sprev = gslo;
#pragma unroll
        for (int rr = 0; rr < 10; rr++) {
            float ycur  = (1.f - 0.3f * MU[rr]) * D[rr];
            float ynext = (rr < 9) ? (1.f - 0.3f * MU[rr + 1]) * D[rr + 1] : gyhi;
            float scur  = S[rr];
            float snext = (rr < 9) ? S[rr + 1] : gshi;
            D[rr] = 0.9f * ycur + 0.05f * (yprev + ynext);
            S[rr] = 0.9f * scur + 0.05f * (sprev + snext);
            yprev = ycur;
            sprev = scur;
        }
    }

    float esum = 0.f;
#pragma unroll
    for (int rr = 0; rr < 10; rr++) {
        int gidx = j * 10 + rr;
        if (gidx >= 8 && gidx < 72) {
            int l = blockIdx.x * 64 + (gidx - 8);
            size_t g = (base + l) * 64 + c;
            hA[g] = 0.5f * (S[rr] + D[rr]);
            hB[g] = 0.5f * (S[rr] - D[rr]);
            esum += 0.5f * MU[rr] * D[rr] * D[rr];
        }
    }

#pragma unroll
    for (int o = 16; o > 0; o >>= 1)
        esum += __shfl_xor_sync(0xffffffffu, esum, o);
    __shared__ float sred[16];
    if ((tid & 31) == 0) sred[tid >> 5] = esum;
    __syncthreads();
    if (tid == 0) {
        float tt = 0.f;
#pragma unroll
        for (int w = 0; w < 16; w++) tt += sred[w];
        g_epart[b * 128 + blockIdx.x] = tt;
    }
}

// ---------------------------------------------------------------------------
__global__ void __launch_bounds__(128) energy_reduce(float* __restrict__ energy)
{
    const int b = blockIdx.x;
    const int tid = threadIdx.x;
    float v = g_epart[b * 128 + tid];
#pragma unroll
    for (int o = 16; o > 0; o >>= 1)
        v += __shfl_xor_sync(0xffffffffu, v, o);
    __shared__ float s[4];
    if ((tid & 31) == 0) s[tid >> 5] = v;
    __syncthreads();
    if (tid == 0) energy[b] = s[0] + s[1] + s[2] + s[3];
}

// ---------------------------------------------------------------------------
extern "C" void kernel_launch(void* const* d_in, const int* in_sizes, int n_in,
                              void* d_out, int out_size)
{
    const float* A  = (const float*)d_in[0];
    const float* Bm = (const float*)d_in[1];
    const float* q  = (const float*)d_in[2];
    const float* W1 = (const float*)d_in[3];
    const float* b1 = (const float*)d_in[4];
    const float* W2 = (const float*)d_in[5];
    const float* b2 = (const float*)d_in[6];
    const float* Wq = (const float*)d_in[7];
    const float* bq = (const float*)d_in[8];

    float* out = (float*)d_out;
    float* hA = out;
    float* hB = out + (size_t)ROWS * 64;
    float* en = out + 2 * (size_t)ROWS * 64;

    static int attr_set = 0;
    if (!attr_set) {
        cudaFuncSetAttribute(mu_kernel,
            cudaFuncAttributeMaxDynamicSharedMemorySize, SMEM_MU);
        attr_set = 1;
    }
    mu_kernel<<<MUGRID, 512, SMEM_MU>>>(A, Bm, q, W1, b1, W2, b2, Wq, bq);

    iter_kernel<<<dim3(LEN / 64, BSZ), 512>>>(A, Bm, hA, hB);

    energy_reduce<<<BSZ, 128>>>(en);
}